// round 3
// baseline (speedup 1.0000x reference)
#include <cuda_runtime.h>
#include <math.h>

#define S 128
#define NRBF 20
#define DEG 16
#define MAXN 10240
#define BN 16
#define PAD 20
#define GMAX 64
#define NS 16

__device__ float g_statef[MAXN * S];
__device__ float g_partial[NS * GMAX * S];

typedef unsigned long long ull;

__device__ __forceinline__ float siluf(float x) {
    return x / (1.0f + expf(-x));
}
__device__ __forceinline__ ull pack2(float a, float b) {
    ull r;
    asm("mov.b64 %0, {%1,%2};" : "=l"(r) : "f"(a), "f"(b));
    return r;
}
__device__ __forceinline__ ull ffma2(ull a, ull b, ull c) {
    ull d;
    asm("fma.rn.f32x2 %0, %1, %2, %3;" : "=l"(d) : "l"(a), "l"(b), "l"(c));
    return d;
}
__device__ __forceinline__ void unpack2(ull p, float& lo, float& hi) {
    asm("mov.b64 {%0,%1}, %2;" : "=f"(lo), "=f"(hi) : "l"(p));
}

union U4 { float4 v; ull p[2]; };

// 4-channel butterfly over 8-lane groups: returns channel (le&3)'s 8-lane sum.
__device__ __forceinline__ float bf4(float q0, float q1, float q2, float q3, int le) {
    const unsigned FULL = 0xffffffffu;
    float a = (le & 1) ? q1 : q0;
    float b = (le & 1) ? q0 : q1;
    a += __shfl_xor_sync(FULL, b, 1);
    float c = (le & 1) ? q3 : q2;
    float d = (le & 1) ? q2 : q3;
    c += __shfl_xor_sync(FULL, d, 1);
    float e = (le & 2) ? c : a;
    float f = (le & 2) ? a : c;
    e += __shfl_xor_sync(FULL, f, 2);
    e += __shfl_xor_sync(FULL, e, 4);
    return e;
}

// ---------------------------------------------------------------------------
// Fused kernel: phi + edge stats + per-node MLP. 16 nodes per 128-thread block.
// ---------------------------------------------------------------------------
__global__ void __launch_bounds__(128) k_main(
        const float* __restrict__ diffs, const float* __restrict__ lens,
        const float* __restrict__ emb0,
        const float* __restrict__ pw1, const float* __restrict__ pb1,
        const float* __restrict__ pw2, const float* __restrict__ pb2,
        const float* __restrict__ filt_w, const float* __restrict__ filt_b,
        const float* __restrict__ u_w, const float* __restrict__ v_w,
        const float* __restrict__ w1, const float* __restrict__ b1,
        const float* __restrict__ w2, const float* __restrict__ b2, int N) {
    __shared__ float h1[S];
    __shared__ float sphi2[S];
    __shared__ float sphi3[S];
    __shared__ __align__(16) float sA[BN][NRBF];
    __shared__ __align__(16) float sB[BN][3][NRBF];
    __shared__ float sAb[BN];
    __shared__ float sBb[BN][3];
    __shared__ float sInv[BN];
    __shared__ __align__(16) float svT[S * PAD];
    __shared__ __align__(16) float ssT[S * PAD];
    __shared__ __align__(16) float vnT[S * PAD];
    __shared__ __align__(16) float hT[S * PAD];
    __shared__ float scp[4][BN];
    __shared__ float sc[BN];

    const unsigned FULL = 0xffffffffu;
    int t = threadIdx.x;
    int n0 = blockIdx.x * BN;

    // ---- Stage 0: phi (only slices [S:3S] are ever used) ----
    {
        float acc = pb1[t];
        #pragma unroll 4
        for (int s = 0; s < S; s++)
            acc += (128.0f * __ldg(&emb0[s])) * pw1[s * S + t];
        h1[t] = siluf(acc);
        __syncthreads();
        float p2 = pb2[S + t];
        float p3 = pb2[2 * S + t];
        #pragma unroll 4
        for (int j = 0; j < S; j++) {
            float h = h1[j];
            p2 += h * pw2[j * 3 * S + S + t];
            p3 += h * pw2[j * 3 * S + 2 * S + t];
        }
        sphi2[t] = p2;
        sphi3[t] = p3;
    }

    // ---- Stage 1: edge statistics. 8 lanes/node, 2 edges/lane ----
    {
        int g8 = t >> 3;
        int le = t & 7;
        int nc = min(n0 + g8, N - 1);
        int e0 = nc * DEG + le * 2;

        float dx0 = diffs[3 * e0 + 0], dy0 = diffs[3 * e0 + 1], dz0 = diffs[3 * e0 + 2];
        float dx1 = diffs[3 * e0 + 3], dy1 = diffs[3 * e0 + 4], dz1 = diffs[3 * e0 + 5];
        float l0 = lens[e0], l1 = lens[e0 + 1];

        float r20 = dx0 * dx0 + dy0 * dy0 + dz0 * dz0;
        float r21 = dx1 * dx1 + dy1 * dy1 + dz1 * dz1;
        float r0 = sqrtf(r20), r1 = sqrtf(r21);
        float m0 = (fabsf(l0) <= 10.0f) ? 1.0f : 0.0f;
        float m1 = (fabsf(l1) <= 10.0f) ? 1.0f : 0.0f;
        float rs0 = fmaxf(r0, 1e-12f), rs1 = fmaxf(r1, 1e-12f);
        float b0 = rs0 * 0.1f, b1e = rs1 * 0.1f;
        float c0 = cospif(b0), c1 = cospif(b1e);
        float s0 = sinpif(b0), s1 = sinpif(b1e);
        float cut0 = (r0 < 10.0f) ? 0.5f * (c0 + 1.0f) : 0.0f;
        float cut1 = (r1 < 10.0f) ? 0.5f * (c1 + 1.0f) : 0.0f;
        float pir0 = m0 * cut0 / rs0;
        float pir1 = m1 * cut1 / rs1;
        float pre0 = m0 * cut0, pre1 = m1 * cut1;

        // frobenius
        float fr = m0 * r20 + m1 * r21;
        fr += __shfl_xor_sync(FULL, fr, 1);
        fr += __shfl_xor_sync(FULL, fr, 2);
        fr += __shfl_xor_sync(FULL, fr, 4);
        if (le == 0) {
            float frob = sqrtf(fr);
            sInv[g8] = 1.0f / ((frob > 0.0f) ? frob : 1.0f);
        }

        // bias sums
        {
            float q0 = pre0 + pre1;
            float q1 = pre0 * dx0 + pre1 * dx1;
            float q2 = pre0 * dy0 + pre1 * dy1;
            float q3 = pre0 * dz0 + pre1 * dz1;
            float v = bf4(q0, q1, q2, q3, le);
            if (le == 0) sAb[g8] = v;
            else if (le < 4) sBb[g8][le - 1] = v;
        }

        // rbf sums via sine recurrence (two independent chains)
        float sk0 = s0, skm0 = 0.0f, cc0 = 2.0f * c0;
        float sk1 = s1, skm1 = 0.0f, cc1 = 2.0f * c1;
        #pragma unroll
        for (int k = 0; k < NRBF; k++) {
            float a0 = pir0 * sk0;
            float a1 = pir1 * sk1;
            float q0 = a0 + a1;
            float q1 = a0 * dx0 + a1 * dx1;
            float q2 = a0 * dy0 + a1 * dy1;
            float q3 = a0 * dz0 + a1 * dz1;
            float v = bf4(q0, q1, q2, q3, le);
            if (le == 0) sA[g8][k] = v;
            else if (le < 4) sB[g8][le - 1][k] = v;
            float sn0 = cc0 * sk0 - skm0; skm0 = sk0; sk0 = sn0;
            float sn1 = cc1 * sk1 - skm1; skm1 = sk1; sk1 = sn1;
        }
    }
    __syncthreads();

    // ---- Stage 2: 20-deep filter dots -> svT/ssT tiles (transposed, pad 20) ----
    {
        int c = t % 3;
        float phi2 = sphi2[t];
        float phi3 = sphi3[t];
        float fb2 = filt_b[S + t];
        float fb3 = filt_b[2 * S + t];

        ull w2p[NRBF / 2], w3p[NRBF / 2];
        #pragma unroll
        for (int kk = 0; kk < NRBF / 2; kk++) {
            w2p[kk] = pack2(filt_w[(2 * kk) * 3 * S + S + t],
                            filt_w[(2 * kk + 1) * 3 * S + S + t]);
            w3p[kk] = pack2(filt_w[(2 * kk) * 3 * S + 2 * S + t],
                            filt_w[(2 * kk + 1) * 3 * S + 2 * S + t]);
        }
        #pragma unroll
        for (int ni = 0; ni < BN; ni++) {
            ull acc2 = 0ull, acc3 = 0ull;
            const ull* pa = (const ull*)&sA[ni][0];
            const ull* pb = (const ull*)&sB[ni][c][0];
            #pragma unroll
            for (int kk = 0; kk < NRBF / 2; kk++) {
                acc2 = ffma2(pa[kk], w2p[kk], acc2);
                acc3 = ffma2(pb[kk], w3p[kk], acc3);
            }
            float a2l, a2h, a3l, a3h;
            unpack2(acc2, a2l, a2h);
            unpack2(acc3, a3l, a3h);
            ssT[t * PAD + ni] = phi2 * (a2l + a2h + sAb[ni] * fb2);
            svT[t * PAD + ni] = phi3 * (a3l + a3h + sBb[ni][c] * fb3) * sInv[ni];
        }
    }
    __syncthreads();

    // ---- Stage 3: U,V matmuls ----
    ull aU[8], aV[8];
    #pragma unroll
    for (int j = 0; j < 8; j++) { aU[j] = 0ull; aV[j] = 0ull; }
    #pragma unroll 2
    for (int s = 0; s < S; s++) {
        float wu = u_w[s * S + t];
        float wv = v_w[s * S + t];
        ull wuu = pack2(wu, wu), wvv = pack2(wv, wv);
        U4 x0, x1, x2, x3;
        x0.v = *(const float4*)&svT[s * PAD + 0];
        x1.v = *(const float4*)&svT[s * PAD + 4];
        x2.v = *(const float4*)&svT[s * PAD + 8];
        x3.v = *(const float4*)&svT[s * PAD + 12];
        aU[0] = ffma2(x0.p[0], wuu, aU[0]); aV[0] = ffma2(x0.p[0], wvv, aV[0]);
        aU[1] = ffma2(x0.p[1], wuu, aU[1]); aV[1] = ffma2(x0.p[1], wvv, aV[1]);
        aU[2] = ffma2(x1.p[0], wuu, aU[2]); aV[2] = ffma2(x1.p[0], wvv, aV[2]);
        aU[3] = ffma2(x1.p[1], wuu, aU[3]); aV[3] = ffma2(x1.p[1], wvv, aV[3]);
        aU[4] = ffma2(x2.p[0], wuu, aU[4]); aV[4] = ffma2(x2.p[0], wvv, aV[4]);
        aU[5] = ffma2(x2.p[1], wuu, aU[5]); aV[5] = ffma2(x2.p[1], wvv, aV[5]);
        aU[6] = ffma2(x3.p[0], wuu, aU[6]); aV[6] = ffma2(x3.p[0], wvv, aV[6]);
        aU[7] = ffma2(x3.p[1], wuu, aU[7]); aV[7] = ffma2(x3.p[1], wvv, aV[7]);
    }

    // c[n] = U.V partial products; Vnorm tiles
    const float SQ3 = 1.7320508075688772f;
    float prod[BN];
    #pragma unroll
    for (int j = 0; j < 8; j++) {
        float u0, u1, v0, v1;
        unpack2(aU[j], u0, u1);
        unpack2(aV[j], v0, v1);
        prod[2 * j] = u0 * v0;
        prod[2 * j + 1] = u1 * v1;
        vnT[t * PAD + 2 * j] = SQ3 * fabsf(v0);
        vnT[t * PAD + 2 * j + 1] = SQ3 * fabsf(v1);
    }
    int warp = t >> 5, lane = t & 31;
    #pragma unroll
    for (int ni = 0; ni < BN; ni++) {
        float v = prod[ni];
        #pragma unroll
        for (int m = 16; m; m >>= 1) v += __shfl_xor_sync(FULL, v, m);
        if (lane == 0) scp[warp][ni] = v;
    }
    __syncthreads();
    if (t < BN) sc[t] = scp[0][t] + scp[1][t] + scp[2][t] + scp[3][t];
    __syncthreads();

    // ---- Stage 4: h = silu([Vnorm, state1] @ upd_w1 + b1) ----
    ull aH[8];
    #pragma unroll
    for (int j = 0; j < 8; j++) aH[j] = 0ull;
    #pragma unroll 2
    for (int s = 0; s < S; s++) {
        float wA = w1[s * S + t];
        float wB = w1[(S + s) * S + t];
        ull wAA = pack2(wA, wA), wBB = pack2(wB, wB);
        U4 x0, x1, x2, x3, y0, y1, y2, y3;
        x0.v = *(const float4*)&vnT[s * PAD + 0];
        x1.v = *(const float4*)&vnT[s * PAD + 4];
        x2.v = *(const float4*)&vnT[s * PAD + 8];
        x3.v = *(const float4*)&vnT[s * PAD + 12];
        y0.v = *(const float4*)&ssT[s * PAD + 0];
        y1.v = *(const float4*)&ssT[s * PAD + 4];
        y2.v = *(const float4*)&ssT[s * PAD + 8];
        y3.v = *(const float4*)&ssT[s * PAD + 12];
        aH[0] = ffma2(x0.p[0], wAA, aH[0]); aH[0] = ffma2(y0.p[0], wBB, aH[0]);
        aH[1] = ffma2(x0.p[1], wAA, aH[1]); aH[1] = ffma2(y0.p[1], wBB, aH[1]);
        aH[2] = ffma2(x1.p[0], wAA, aH[2]); aH[2] = ffma2(y1.p[0], wBB, aH[2]);
        aH[3] = ffma2(x1.p[1], wAA, aH[3]); aH[3] = ffma2(y1.p[1], wBB, aH[3]);
        aH[4] = ffma2(x2.p[0], wAA, aH[4]); aH[4] = ffma2(y2.p[0], wBB, aH[4]);
        aH[5] = ffma2(x2.p[1], wAA, aH[5]); aH[5] = ffma2(y2.p[1], wBB, aH[5]);
        aH[6] = ffma2(x3.p[0], wAA, aH[6]); aH[6] = ffma2(y3.p[0], wBB, aH[6]);
        aH[7] = ffma2(x3.p[1], wAA, aH[7]); aH[7] = ffma2(y3.p[1], wBB, aH[7]);
    }
    {
        float bb = b1[t];
        #pragma unroll
        for (int j = 0; j < 8; j++) {
            float h0, h1v;
            unpack2(aH[j], h0, h1v);
            hT[t * PAD + 2 * j] = siluf(h0 + bb);
            hT[t * PAD + 2 * j + 1] = siluf(h1v + bb);
        }
    }
    __syncthreads();

    // ---- Stage 5: a_sv, a_ss; final state ----
    ull aSV[8], aSS[8];
    #pragma unroll
    for (int j = 0; j < 8; j++) { aSV[j] = 0ull; aSS[j] = 0ull; }
    #pragma unroll 2
    for (int s = 0; s < S; s++) {
        float wsv = w2[s * 3 * S + S + t];
        float wss = w2[s * 3 * S + 2 * S + t];
        ull wv2 = pack2(wsv, wsv), ws2 = pack2(wss, wss);
        U4 x0, x1, x2, x3;
        x0.v = *(const float4*)&hT[s * PAD + 0];
        x1.v = *(const float4*)&hT[s * PAD + 4];
        x2.v = *(const float4*)&hT[s * PAD + 8];
        x3.v = *(const float4*)&hT[s * PAD + 12];
        aSV[0] = ffma2(x0.p[0], wv2, aSV[0]); aSS[0] = ffma2(x0.p[0], ws2, aSS[0]);
        aSV[1] = ffma2(x0.p[1], wv2, aSV[1]); aSS[1] = ffma2(x0.p[1], ws2, aSS[1]);
        aSV[2] = ffma2(x1.p[0], wv2, aSV[2]); aSS[2] = ffma2(x1.p[0], ws2, aSS[2]);
        aSV[3] = ffma2(x1.p[1], wv2, aSV[3]); aSS[3] = ffma2(x1.p[1], ws2, aSS[3]);
        aSV[4] = ffma2(x2.p[0], wv2, aSV[4]); aSS[4] = ffma2(x2.p[0], ws2, aSS[4]);
        aSV[5] = ffma2(x2.p[1], wv2, aSV[5]); aSS[5] = ffma2(x2.p[1], ws2, aSS[5]);
        aSV[6] = ffma2(x3.p[0], wv2, aSV[6]); aSS[6] = ffma2(x3.p[0], ws2, aSS[6]);
        aSV[7] = ffma2(x3.p[1], wv2, aSV[7]); aSS[7] = ffma2(x3.p[1], ws2, aSS[7]);
    }
    {
        float bsv = b2[S + t];
        float bss = b2[2 * S + t];
        #pragma unroll
        for (int j = 0; j < 8; j++) {
            float sv0, sv1, ss0, ss1;
            unpack2(aSV[j], sv0, sv1);
            unpack2(aSS[j], ss0, ss1);
            int nn0 = n0 + 2 * j;
            if (nn0 < N)
                g_statef[nn0 * S + t] = (ss0 + bss) + 3.0f * sc[2 * j] * (sv0 + bsv);
            if (nn0 + 1 < N)
                g_statef[(nn0 + 1) * S + t] = (ss1 + bss) + 3.0f * sc[2 * j + 1] * (sv1 + bsv);
        }
    }
}

// ---------------------------------------------------------------------------
// Graph segment-sum: grid (G, NS). Block (g, stripe) scans its gidx stripe.
// Deterministic: sequential within stripe, stripes combined in order in k_out.
// ---------------------------------------------------------------------------
__global__ void __launch_bounds__(128) k_gp(const int* __restrict__ gidx, int N) {
    __shared__ int sgi[128];
    int g = blockIdx.x;
    int G = gridDim.x;
    int stripe = blockIdx.y;
    int t = threadIdx.x;
    int per = (N + NS - 1) / NS;
    int n0 = stripe * per;
    int n1 = min(n0 + per, N);
    float acc = 0.0f;
    for (int c0 = n0; c0 < n1; c0 += 128) {
        int cl = min(128, n1 - c0);
        __syncthreads();
        if (t < cl) sgi[t] = gidx[c0 + t];
        __syncthreads();
        for (int j = 0; j < cl; j++) {
            if (sgi[j] == g) acc += g_statef[(c0 + j) * S + t];
        }
    }
    g_partial[(stripe * G + g) * S + t] = acc;
}

// ---------------------------------------------------------------------------
// Combine stripes + output MLP per graph
// ---------------------------------------------------------------------------
__global__ void k_out(const float* __restrict__ w1, const float* __restrict__ b1,
                      const float* __restrict__ w2, const float* __restrict__ b2,
                      float* __restrict__ out, int G) {
    __shared__ float gs[S];
    __shared__ float red[4];
    int g = blockIdx.x, t = threadIdx.x;
    float acc = 0.0f;
    #pragma unroll
    for (int st = 0; st < NS; st++)
        acc += g_partial[(st * G + g) * S + t];
    gs[t] = acc;
    __syncthreads();
    float hacc = b1[t];
    #pragma unroll 4
    for (int s = 0; s < S; s++) hacc += gs[s] * w1[s * S + t];
    float h = hacc / (1.0f + expf(-hacc));
    float p = h * w2[t];
    #pragma unroll
    for (int m = 16; m; m >>= 1) p += __shfl_xor_sync(0xffffffffu, p, m);
    int warp = t >> 5, lane = t & 31;
    if (lane == 0) red[warp] = p;
    __syncthreads();
    if (t == 0) out[g] = red[0] + red[1] + red[2] + red[3] + b2[0];
}

// ---------------------------------------------------------------------------
extern "C" void kernel_launch(void* const* d_in, const int* in_sizes, int n_in,
                              void* d_out, int out_size) {
    int N = in_sizes[3];                 // node_graph_index
    int off = (n_in >= 22) ? 1 : 0;      // num_graphs scalar present?

    const float* diffs   = (const float*)d_in[0];
    const float* lens    = (const float*)d_in[1];
    const int*   gidx    = (const int*)d_in[3];
    const float* emb0    = (const float*)d_in[4 + off];
    const float* phi_w1  = (const float*)d_in[5 + off];
    const float* phi_b1  = (const float*)d_in[6 + off];
    const float* phi_w2  = (const float*)d_in[7 + off];
    const float* phi_b2  = (const float*)d_in[8 + off];
    const float* filt_w  = (const float*)d_in[9 + off];
    const float* filt_b  = (const float*)d_in[10 + off];
    const float* u_w     = (const float*)d_in[11 + off];
    const float* v_w     = (const float*)d_in[12 + off];
    const float* upd_w1  = (const float*)d_in[13 + off];
    const float* upd_b1  = (const float*)d_in[14 + off];
    const float* upd_w2  = (const float*)d_in[15 + off];
    const float* upd_b2  = (const float*)d_in[16 + off];
    const float* out_w1  = (const float*)d_in[17 + off];
    const float* out_b1  = (const float*)d_in[18 + off];
    const float* out_w2  = (const float*)d_in[19 + off];
    const float* out_b2  = (const float*)d_in[20 + off];
    float* out = (float*)d_out;
    int G = out_size;

    int nblk = (N + BN - 1) / BN;
    k_main<<<nblk, 128>>>(diffs, lens, emb0, phi_w1, phi_b1, phi_w2, phi_b2,
                          filt_w, filt_b, u_w, v_w,
                          upd_w1, upd_b1, upd_w2, upd_b2, N);

    dim3 ggrid(G, NS);
    k_gp<<<ggrid, 128>>>(gidx, N);

    k_out<<<G, 128>>>(out_w1, out_b1, out_w2, out_b2, out, G);
}

// round 4
// speedup vs baseline: 1.1281x; 1.1281x over previous
#include <cuda_runtime.h>
#include <math.h>

#define S 128
#define NRBF 20
#define DEG 16
#define MAXN 10240
#define NPB 16        // nodes per block in k_edge
#define BN 32         // nodes per block in k_node
#define BW 36         // padded tile width
#define GMAX 64
#define NS 16

__device__ float g_phi[3 * S];
__device__ float g_state1[MAXN * S];
__device__ float g_vsum[MAXN * S];
__device__ float g_statef[MAXN * S];
__device__ float g_partial[NS * GMAX * S];

typedef unsigned long long ull;

__device__ __forceinline__ float siluf(float x) {
    return x / (1.0f + expf(-x));
}
__device__ __forceinline__ ull pack2(float a, float b) {
    ull r;
    asm("mov.b64 %0, {%1,%2};" : "=l"(r) : "f"(a), "f"(b));
    return r;
}
__device__ __forceinline__ ull ffma2(ull a, ull b, ull c) {
    ull d;
    asm("fma.rn.f32x2 %0, %1, %2, %3;" : "=l"(d) : "l"(a), "l"(b), "l"(c));
    return d;
}
__device__ __forceinline__ void unpack2(ull p, float& lo, float& hi) {
    asm("mov.b64 {%0,%1}, %2;" : "=f"(lo), "=f"(hi) : "l"(p));
}

union U4 { float4 v; ull p[2]; };

// 4-channel butterfly over 8-lane groups
__device__ __forceinline__ float bf4(float q0, float q1, float q2, float q3, int le) {
    const unsigned FULL = 0xffffffffu;
    float a = (le & 1) ? q1 : q0;
    float b = (le & 1) ? q0 : q1;
    a += __shfl_xor_sync(FULL, b, 1);
    float c = (le & 1) ? q3 : q2;
    float d = (le & 1) ? q2 : q3;
    c += __shfl_xor_sync(FULL, d, 1);
    float e = (le & 2) ? c : a;
    float f = (le & 2) ? a : c;
    e += __shfl_xor_sync(FULL, f, 2);
    e += __shfl_xor_sync(FULL, e, 4);
    return e;
}

// ---------------------------------------------------------------------------
// Kernel 0: phi vector (single 384-vector since initial state is uniform)
// ---------------------------------------------------------------------------
__global__ void k_phi(const float* __restrict__ emb0,
                      const float* __restrict__ w1, const float* __restrict__ b1,
                      const float* __restrict__ w2, const float* __restrict__ b2) {
    __shared__ float h1[S];
    int t = threadIdx.x;
    if (t < S) {
        float acc = b1[t];
        #pragma unroll 4
        for (int s = 0; s < S; s++)
            acc += (128.0f * emb0[s]) * w1[s * S + t];
        h1[t] = siluf(acc);
    }
    __syncthreads();
    if (t < 3 * S) {
        float acc = b2[t];
        #pragma unroll 4
        for (int j = 0; j < S; j++)
            acc += h1[j] * w2[j * 3 * S + t];
        g_phi[t] = acc;
    }
}

// ---------------------------------------------------------------------------
// Kernel 1: edge statistics + filter dots -> g_state1, g_vsum.
// 16 nodes/block, 8 lanes/node, 2 edges/lane.
// ---------------------------------------------------------------------------
__global__ void __launch_bounds__(128) k_edge(
        const float* __restrict__ diffs, const float* __restrict__ lens,
        const float* __restrict__ filt_w, const float* __restrict__ filt_b,
        int N) {
    __shared__ __align__(16) float sA[NPB][NRBF];
    __shared__ __align__(16) float sB[NPB][3][NRBF];
    __shared__ float sAb[NPB];
    __shared__ float sBb[NPB][3];
    __shared__ float sInv[NPB];

    const unsigned FULL = 0xffffffffu;
    int t = threadIdx.x;
    int n0 = blockIdx.x * NPB;

    {
        int g8 = t >> 3;
        int le = t & 7;
        int nc = min(n0 + g8, N - 1);
        int e0 = nc * DEG + le * 2;

        float dx0 = diffs[3 * e0 + 0], dy0 = diffs[3 * e0 + 1], dz0 = diffs[3 * e0 + 2];
        float dx1 = diffs[3 * e0 + 3], dy1 = diffs[3 * e0 + 4], dz1 = diffs[3 * e0 + 5];
        float l0 = lens[e0], l1 = lens[e0 + 1];

        float r20 = dx0 * dx0 + dy0 * dy0 + dz0 * dz0;
        float r21 = dx1 * dx1 + dy1 * dy1 + dz1 * dz1;
        float r0 = sqrtf(r20), r1 = sqrtf(r21);
        float m0 = (fabsf(l0) <= 10.0f) ? 1.0f : 0.0f;
        float m1 = (fabsf(l1) <= 10.0f) ? 1.0f : 0.0f;
        float rs0 = fmaxf(r0, 1e-12f), rs1 = fmaxf(r1, 1e-12f);
        float b0 = rs0 * 0.1f, b1e = rs1 * 0.1f;
        float c0 = cospif(b0), c1 = cospif(b1e);
        float s0 = sinpif(b0), s1 = sinpif(b1e);
        float cut0 = (r0 < 10.0f) ? 0.5f * (c0 + 1.0f) : 0.0f;
        float cut1 = (r1 < 10.0f) ? 0.5f * (c1 + 1.0f) : 0.0f;
        float pir0 = m0 * cut0 / rs0;
        float pir1 = m1 * cut1 / rs1;
        float pre0 = m0 * cut0, pre1 = m1 * cut1;

        float fr = m0 * r20 + m1 * r21;
        fr += __shfl_xor_sync(FULL, fr, 1);
        fr += __shfl_xor_sync(FULL, fr, 2);
        fr += __shfl_xor_sync(FULL, fr, 4);
        if (le == 0) {
            float frob = sqrtf(fr);
            sInv[g8] = 1.0f / ((frob > 0.0f) ? frob : 1.0f);
        }

        {
            float q0 = pre0 + pre1;
            float q1 = pre0 * dx0 + pre1 * dx1;
            float q2 = pre0 * dy0 + pre1 * dy1;
            float q3 = pre0 * dz0 + pre1 * dz1;
            float v = bf4(q0, q1, q2, q3, le);
            if (le == 0) sAb[g8] = v;
            else if (le < 4) sBb[g8][le - 1] = v;
        }

        float sk0 = s0, skm0 = 0.0f, cc0 = 2.0f * c0;
        float sk1 = s1, skm1 = 0.0f, cc1 = 2.0f * c1;
        #pragma unroll
        for (int k = 0; k < NRBF; k++) {
            float a0 = pir0 * sk0;
            float a1 = pir1 * sk1;
            float q0 = a0 + a1;
            float q1 = a0 * dx0 + a1 * dx1;
            float q2 = a0 * dy0 + a1 * dy1;
            float q3 = a0 * dz0 + a1 * dz1;
            float v = bf4(q0, q1, q2, q3, le);
            if (le == 0) sA[g8][k] = v;
            else if (le < 4) sB[g8][le - 1][k] = v;
            float sn0 = cc0 * sk0 - skm0; skm0 = sk0; sk0 = sn0;
            float sn1 = cc1 * sk1 - skm1; skm1 = sk1; sk1 = sn1;
        }
    }
    __syncthreads();

    // filter dots per (node, feature)
    {
        int c = t % 3;
        float phi2 = g_phi[S + t];
        float phi3 = g_phi[2 * S + t];
        float fb2 = filt_b[S + t];
        float fb3 = filt_b[2 * S + t];

        ull w2p[NRBF / 2], w3p[NRBF / 2];
        #pragma unroll
        for (int kk = 0; kk < NRBF / 2; kk++) {
            w2p[kk] = pack2(filt_w[(2 * kk) * 3 * S + S + t],
                            filt_w[(2 * kk + 1) * 3 * S + S + t]);
            w3p[kk] = pack2(filt_w[(2 * kk) * 3 * S + 2 * S + t],
                            filt_w[(2 * kk + 1) * 3 * S + 2 * S + t]);
        }
        #pragma unroll
        for (int ni = 0; ni < NPB; ni++) {
            int nn = n0 + ni;
            if (nn >= N) break;
            ull acc2 = 0ull, acc3 = 0ull;
            const ull* pa = (const ull*)&sA[ni][0];
            const ull* pb = (const ull*)&sB[ni][c][0];
            #pragma unroll
            for (int kk = 0; kk < NRBF / 2; kk++) {
                acc2 = ffma2(pa[kk], w2p[kk], acc2);
                acc3 = ffma2(pb[kk], w3p[kk], acc3);
            }
            float a2l, a2h, a3l, a3h;
            unpack2(acc2, a2l, a2h);
            unpack2(acc3, a3l, a3h);
            g_state1[nn * S + t] = phi2 * (a2l + a2h + sAb[ni] * fb2);
            g_vsum[nn * S + t] = phi3 * (a3l + a3h + sBb[ni][c] * fb3) * sInv[ni];
        }
    }
}

// ---------------------------------------------------------------------------
// Kernel 2: per-node MLP. BN=32 nodes/block, 256 threads (2 halves x 16 nodes).
// Buffer A: sv -> vn -> h (reused); Buffer B: ss.
// ---------------------------------------------------------------------------
__global__ void __launch_bounds__(256) k_node(
        const float* __restrict__ u_w, const float* __restrict__ v_w,
        const float* __restrict__ w1, const float* __restrict__ b1,
        const float* __restrict__ w2, const float* __restrict__ b2, int N) {
    __shared__ __align__(16) float bufA[S * BW];
    __shared__ __align__(16) float bufB[S * BW];
    __shared__ float scp[8][16];
    __shared__ float sc[BN];

    const unsigned FULL = 0xffffffffu;
    int t = threadIdx.x;
    int f = t & 127;
    int h = t >> 7;
    int colbase = 16 * h;
    int n0 = blockIdx.x * BN;

    // fill tiles (each half fills its 16 columns)
    #pragma unroll
    for (int ni = 0; ni < 16; ni++) {
        int col = colbase + ni;
        int nn = min(n0 + col, N - 1);
        bufA[f * BW + col] = g_vsum[nn * S + f];
        bufB[f * BW + col] = g_state1[nn * S + f];
    }
    __syncthreads();

    // U, V matmuls
    ull aU[8], aV[8];
    #pragma unroll
    for (int j = 0; j < 8; j++) { aU[j] = 0ull; aV[j] = 0ull; }
    #pragma unroll 2
    for (int s = 0; s < S; s++) {
        float wu = u_w[s * S + f];
        float wv = v_w[s * S + f];
        ull wuu = pack2(wu, wu), wvv = pack2(wv, wv);
        U4 x0, x1, x2, x3;
        x0.v = *(const float4*)&bufA[s * BW + colbase + 0];
        x1.v = *(const float4*)&bufA[s * BW + colbase + 4];
        x2.v = *(const float4*)&bufA[s * BW + colbase + 8];
        x3.v = *(const float4*)&bufA[s * BW + colbase + 12];
        aU[0] = ffma2(x0.p[0], wuu, aU[0]); aV[0] = ffma2(x0.p[0], wvv, aV[0]);
        aU[1] = ffma2(x0.p[1], wuu, aU[1]); aV[1] = ffma2(x0.p[1], wvv, aV[1]);
        aU[2] = ffma2(x1.p[0], wuu, aU[2]); aV[2] = ffma2(x1.p[0], wvv, aV[2]);
        aU[3] = ffma2(x1.p[1], wuu, aU[3]); aV[3] = ffma2(x1.p[1], wvv, aV[3]);
        aU[4] = ffma2(x2.p[0], wuu, aU[4]); aV[4] = ffma2(x2.p[0], wvv, aV[4]);
        aU[5] = ffma2(x2.p[1], wuu, aU[5]); aV[5] = ffma2(x2.p[1], wvv, aV[5]);
        aU[6] = ffma2(x3.p[0], wuu, aU[6]); aV[6] = ffma2(x3.p[0], wvv, aV[6]);
        aU[7] = ffma2(x3.p[1], wuu, aU[7]); aV[7] = ffma2(x3.p[1], wvv, aV[7]);
    }
    __syncthreads();   // everyone done reading bufA(sv)

    // prod for c[n]; Vnorm into bufA
    const float SQ3 = 1.7320508075688772f;
    float prod[16];
    #pragma unroll
    for (int j = 0; j < 8; j++) {
        float u0, u1, v0, v1;
        unpack2(aU[j], u0, u1);
        unpack2(aV[j], v0, v1);
        prod[2 * j] = u0 * v0;
        prod[2 * j + 1] = u1 * v1;
        bufA[f * BW + colbase + 2 * j] = SQ3 * fabsf(v0);
        bufA[f * BW + colbase + 2 * j + 1] = SQ3 * fabsf(v1);
    }
    int w = t >> 5, lane = t & 31;
    #pragma unroll
    for (int ni = 0; ni < 16; ni++) {
        float v = prod[ni];
        #pragma unroll
        for (int m = 16; m; m >>= 1) v += __shfl_xor_sync(FULL, v, m);
        if (lane == 0) scp[w][ni] = v;
    }
    __syncthreads();
    if (t < BN) {
        int hh = t >> 4, ni = t & 15;
        int wb = hh * 4;
        sc[t] = scp[wb][ni] + scp[wb + 1][ni] + scp[wb + 2][ni] + scp[wb + 3][ni];
    }
    __syncthreads();

    // h = silu([Vnorm, state1] @ upd_w1 + b1)
    ull aH[8];
    #pragma unroll
    for (int j = 0; j < 8; j++) aH[j] = 0ull;
    #pragma unroll 2
    for (int s = 0; s < S; s++) {
        float wA = w1[s * S + f];
        float wB = w1[(S + s) * S + f];
        ull wAA = pack2(wA, wA), wBB = pack2(wB, wB);
        U4 x0, x1, x2, x3, y0, y1, y2, y3;
        x0.v = *(const float4*)&bufA[s * BW + colbase + 0];
        x1.v = *(const float4*)&bufA[s * BW + colbase + 4];
        x2.v = *(const float4*)&bufA[s * BW + colbase + 8];
        x3.v = *(const float4*)&bufA[s * BW + colbase + 12];
        y0.v = *(const float4*)&bufB[s * BW + colbase + 0];
        y1.v = *(const float4*)&bufB[s * BW + colbase + 4];
        y2.v = *(const float4*)&bufB[s * BW + colbase + 8];
        y3.v = *(const float4*)&bufB[s * BW + colbase + 12];
        aH[0] = ffma2(x0.p[0], wAA, aH[0]); aH[0] = ffma2(y0.p[0], wBB, aH[0]);
        aH[1] = ffma2(x0.p[1], wAA, aH[1]); aH[1] = ffma2(y0.p[1], wBB, aH[1]);
        aH[2] = ffma2(x1.p[0], wAA, aH[2]); aH[2] = ffma2(y1.p[0], wBB, aH[2]);
        aH[3] = ffma2(x1.p[1], wAA, aH[3]); aH[3] = ffma2(y1.p[1], wBB, aH[3]);
        aH[4] = ffma2(x2.p[0], wAA, aH[4]); aH[4] = ffma2(y2.p[0], wBB, aH[4]);
        aH[5] = ffma2(x2.p[1], wAA, aH[5]); aH[5] = ffma2(y2.p[1], wBB, aH[5]);
        aH[6] = ffma2(x3.p[0], wAA, aH[6]); aH[6] = ffma2(y3.p[0], wBB, aH[6]);
        aH[7] = ffma2(x3.p[1], wAA, aH[7]); aH[7] = ffma2(y3.p[1], wBB, aH[7]);
    }
    __syncthreads();   // done reading bufA(vn) + bufB(ss)
    {
        float bb = b1[f];
        #pragma unroll
        for (int j = 0; j < 8; j++) {
            float h0, h1v;
            unpack2(aH[j], h0, h1v);
            bufA[f * BW + colbase + 2 * j] = siluf(h0 + bb);
            bufA[f * BW + colbase + 2 * j + 1] = siluf(h1v + bb);
        }
    }
    __syncthreads();

    // a_sv, a_ss; final state
    ull aSV[8], aSS[8];
    #pragma unroll
    for (int j = 0; j < 8; j++) { aSV[j] = 0ull; aSS[j] = 0ull; }
    #pragma unroll 2
    for (int s = 0; s < S; s++) {
        float wsv = w2[s * 3 * S + S + f];
        float wss = w2[s * 3 * S + 2 * S + f];
        ull wv2 = pack2(wsv, wsv), ws2 = pack2(wss, wss);
        U4 x0, x1, x2, x3;
        x0.v = *(const float4*)&bufA[s * BW + colbase + 0];
        x1.v = *(const float4*)&bufA[s * BW + colbase + 4];
        x2.v = *(const float4*)&bufA[s * BW + colbase + 8];
        x3.v = *(const float4*)&bufA[s * BW + colbase + 12];
        aSV[0] = ffma2(x0.p[0], wv2, aSV[0]); aSS[0] = ffma2(x0.p[0], ws2, aSS[0]);
        aSV[1] = ffma2(x0.p[1], wv2, aSV[1]); aSS[1] = ffma2(x0.p[1], ws2, aSS[1]);
        aSV[2] = ffma2(x1.p[0], wv2, aSV[2]); aSS[2] = ffma2(x1.p[0], ws2, aSS[2]);
        aSV[3] = ffma2(x1.p[1], wv2, aSV[3]); aSS[3] = ffma2(x1.p[1], ws2, aSS[3]);
        aSV[4] = ffma2(x2.p[0], wv2, aSV[4]); aSS[4] = ffma2(x2.p[0], ws2, aSS[4]);
        aSV[5] = ffma2(x2.p[1], wv2, aSV[5]); aSS[5] = ffma2(x2.p[1], ws2, aSS[5]);
        aSV[6] = ffma2(x3.p[0], wv2, aSV[6]); aSS[6] = ffma2(x3.p[0], ws2, aSS[6]);
        aSV[7] = ffma2(x3.p[1], wv2, aSV[7]); aSS[7] = ffma2(x3.p[1], ws2, aSS[7]);
    }
    {
        float bsv = b2[S + f];
        float bss = b2[2 * S + f];
        #pragma unroll
        for (int j = 0; j < 8; j++) {
            float sv0, sv1, ss0, ss1;
            unpack2(aSV[j], sv0, sv1);
            unpack2(aSS[j], ss0, ss1);
            int col = colbase + 2 * j;
            int nn0 = n0 + col;
            if (nn0 < N)
                g_statef[nn0 * S + f] = (ss0 + bss) + 3.0f * sc[col] * (sv0 + bsv);
            if (nn0 + 1 < N)
                g_statef[(nn0 + 1) * S + f] = (ss1 + bss) + 3.0f * sc[col + 1] * (sv1 + bsv);
        }
    }
}

// ---------------------------------------------------------------------------
// Graph segment-sum: grid (G, NS), deterministic stripes.
// ---------------------------------------------------------------------------
__global__ void __launch_bounds__(128) k_gp(const int* __restrict__ gidx, int N) {
    __shared__ int sgi[128];
    int g = blockIdx.x;
    int G = gridDim.x;
    int stripe = blockIdx.y;
    int t = threadIdx.x;
    int per = (N + NS - 1) / NS;
    int n0 = stripe * per;
    int n1 = min(n0 + per, N);
    float acc = 0.0f;
    for (int c0 = n0; c0 < n1; c0 += 128) {
        int cl = min(128, n1 - c0);
        __syncthreads();
        if (t < cl) sgi[t] = gidx[c0 + t];
        __syncthreads();
        for (int j = 0; j < cl; j++) {
            if (sgi[j] == g) acc += g_statef[(c0 + j) * S + t];
        }
    }
    g_partial[(stripe * G + g) * S + t] = acc;
}

// ---------------------------------------------------------------------------
// Combine stripes + output MLP per graph
// ---------------------------------------------------------------------------
__global__ void k_out(const float* __restrict__ w1, const float* __restrict__ b1,
                      const float* __restrict__ w2, const float* __restrict__ b2,
                      float* __restrict__ out, int G) {
    __shared__ float gs[S];
    __shared__ float red[4];
    int g = blockIdx.x, t = threadIdx.x;
    float acc = 0.0f;
    #pragma unroll
    for (int st = 0; st < NS; st++)
        acc += g_partial[(st * G + g) * S + t];
    gs[t] = acc;
    __syncthreads();
    float hacc = b1[t];
    #pragma unroll 4
    for (int s = 0; s < S; s++) hacc += gs[s] * w1[s * S + t];
    float h = hacc / (1.0f + expf(-hacc));
    float p = h * w2[t];
    #pragma unroll
    for (int m = 16; m; m >>= 1) p += __shfl_xor_sync(0xffffffffu, p, m);
    int w = t >> 5, lane = t & 31;
    if (lane == 0) red[w] = p;
    __syncthreads();
    if (t == 0) out[g] = red[0] + red[1] + red[2] + red[3] + b2[0];
}

// ---------------------------------------------------------------------------
extern "C" void kernel_launch(void* const* d_in, const int* in_sizes, int n_in,
                              void* d_out, int out_size) {
    int N = in_sizes[3];
    int off = (n_in >= 22) ? 1 : 0;

    const float* diffs   = (const float*)d_in[0];
    const float* lens    = (const float*)d_in[1];
    const int*   gidx    = (const int*)d_in[3];
    const float* emb0    = (const float*)d_in[4 + off];
    const float* phi_w1  = (const float*)d_in[5 + off];
    const float* phi_b1  = (const float*)d_in[6 + off];
    const float* phi_w2  = (const float*)d_in[7 + off];
    const float* phi_b2  = (const float*)d_in[8 + off];
    const float* filt_w  = (const float*)d_in[9 + off];
    const float* filt_b  = (const float*)d_in[10 + off];
    const float* u_w     = (const float*)d_in[11 + off];
    const float* v_w     = (const float*)d_in[12 + off];
    const float* upd_w1  = (const float*)d_in[13 + off];
    const float* upd_b1  = (const float*)d_in[14 + off];
    const float* upd_w2  = (const float*)d_in[15 + off];
    const float* upd_b2  = (const float*)d_in[16 + off];
    const float* out_w1  = (const float*)d_in[17 + off];
    const float* out_b1  = (const float*)d_in[18 + off];
    const float* out_w2  = (const float*)d_in[19 + off];
    const float* out_b2  = (const float*)d_in[20 + off];
    float* out = (float*)d_out;
    int G = out_size;

    k_phi<<<1, 3 * S>>>(emb0, phi_w1, phi_b1, phi_w2, phi_b2);

    int nblk1 = (N + NPB - 1) / NPB;
    k_edge<<<nblk1, 128>>>(diffs, lens, filt_w, filt_b, N);

    int nblk2 = (N + BN - 1) / BN;
    k_node<<<nblk2, 256>>>(u_w, v_w, upd_w1, upd_b1, upd_w2, upd_b2, N);

    dim3 ggrid(G, NS);
    k_gp<<<ggrid, 128>>>(gidx, N);

    k_out<<<G, 128>>>(out_w1, out_b1, out_w2, out_b2, out, G);
}

// round 5
// speedup vs baseline: 1.2910x; 1.1444x over previous
#include <cuda_runtime.h>
#include <math.h>

#define S 128
#define NRBF 20
#define DEG 16
#define NPB 16        // nodes per block in k_edge
#define BN 32         // nodes per block in k_node
#define BW 36         // padded tile width
#define GMAX 64

__device__ float g_phi[3 * S];
__device__ float g_state1[10240 * S];
__device__ float g_vsum[10240 * S];
__device__ float g_graph[GMAX * S];

typedef unsigned long long ull;

__device__ __forceinline__ float siluf(float x) {
    return x / (1.0f + expf(-x));
}
__device__ __forceinline__ ull pack2(float a, float b) {
    ull r;
    asm("mov.b64 %0, {%1,%2};" : "=l"(r) : "f"(a), "f"(b));
    return r;
}
__device__ __forceinline__ ull ffma2(ull a, ull b, ull c) {
    ull d;
    asm("fma.rn.f32x2 %0, %1, %2, %3;" : "=l"(d) : "l"(a), "l"(b), "l"(c));
    return d;
}
__device__ __forceinline__ void unpack2(ull p, float& lo, float& hi) {
    asm("mov.b64 {%0,%1}, %2;" : "=f"(lo), "=f"(hi) : "l"(p));
}

union U4 { float4 v; ull p[2]; };

// 4-channel butterfly over 8-lane groups
__device__ __forceinline__ float bf4(float q0, float q1, float q2, float q3, int le) {
    const unsigned FULL = 0xffffffffu;
    float a = (le & 1) ? q1 : q0;
    float b = (le & 1) ? q0 : q1;
    a += __shfl_xor_sync(FULL, b, 1);
    float c = (le & 1) ? q3 : q2;
    float d = (le & 1) ? q2 : q3;
    c += __shfl_xor_sync(FULL, d, 1);
    float e = (le & 2) ? c : a;
    float f = (le & 2) ? a : c;
    e += __shfl_xor_sync(FULL, f, 2);
    e += __shfl_xor_sync(FULL, e, 4);
    return e;
}

// ---------------------------------------------------------------------------
// Kernel 0: phi vector + zero graph accumulator
// ---------------------------------------------------------------------------
__global__ void k_phi(const float* __restrict__ emb0,
                      const float* __restrict__ w1, const float* __restrict__ b1,
                      const float* __restrict__ w2, const float* __restrict__ b2) {
    __shared__ float h1[S];
    int t = threadIdx.x;
    // zero graph accumulator (stream-ordered before k_node's atomics)
    for (int i = t; i < GMAX * S; i += 384) g_graph[i] = 0.0f;
    if (t < S) {
        float acc = b1[t];
        #pragma unroll 4
        for (int s = 0; s < S; s++)
            acc += (128.0f * emb0[s]) * w1[s * S + t];
        h1[t] = siluf(acc);
    }
    __syncthreads();
    if (t < 3 * S) {
        float acc = b2[t];
        #pragma unroll 4
        for (int j = 0; j < S; j++)
            acc += h1[j] * w2[j * 3 * S + t];
        g_phi[t] = acc;
    }
}

// ---------------------------------------------------------------------------
// Kernel 1: edge statistics + filter dots -> g_state1, g_vsum.
// 16 nodes/block, 8 lanes/node, 2 edges/lane.
// ---------------------------------------------------------------------------
__global__ void __launch_bounds__(128) k_edge(
        const float* __restrict__ diffs, const float* __restrict__ lens,
        const float* __restrict__ filt_w, const float* __restrict__ filt_b,
        int N) {
    __shared__ __align__(16) float sA[NPB][NRBF];
    __shared__ __align__(16) float sB[NPB][3][NRBF];
    __shared__ float sAb[NPB];
    __shared__ float sBb[NPB][3];
    __shared__ float sInv[NPB];

    const unsigned FULL = 0xffffffffu;
    int t = threadIdx.x;
    int n0 = blockIdx.x * NPB;

    {
        int g8 = t >> 3;
        int le = t & 7;
        int nc = min(n0 + g8, N - 1);
        int e0 = nc * DEG + le * 2;

        float dx0 = diffs[3 * e0 + 0], dy0 = diffs[3 * e0 + 1], dz0 = diffs[3 * e0 + 2];
        float dx1 = diffs[3 * e0 + 3], dy1 = diffs[3 * e0 + 4], dz1 = diffs[3 * e0 + 5];
        float l0 = lens[e0], l1 = lens[e0 + 1];

        float r20 = dx0 * dx0 + dy0 * dy0 + dz0 * dz0;
        float r21 = dx1 * dx1 + dy1 * dy1 + dz1 * dz1;
        float r0 = sqrtf(r20), r1 = sqrtf(r21);
        float m0 = (fabsf(l0) <= 10.0f) ? 1.0f : 0.0f;
        float m1 = (fabsf(l1) <= 10.0f) ? 1.0f : 0.0f;
        float rs0 = fmaxf(r0, 1e-12f), rs1 = fmaxf(r1, 1e-12f);
        float b0 = rs0 * 0.1f, b1e = rs1 * 0.1f;
        float c0 = cospif(b0), c1 = cospif(b1e);
        float s0 = sinpif(b0), s1 = sinpif(b1e);
        float cut0 = (r0 < 10.0f) ? 0.5f * (c0 + 1.0f) : 0.0f;
        float cut1 = (r1 < 10.0f) ? 0.5f * (c1 + 1.0f) : 0.0f;
        float pir0 = m0 * cut0 / rs0;
        float pir1 = m1 * cut1 / rs1;
        float pre0 = m0 * cut0, pre1 = m1 * cut1;

        float fr = m0 * r20 + m1 * r21;
        fr += __shfl_xor_sync(FULL, fr, 1);
        fr += __shfl_xor_sync(FULL, fr, 2);
        fr += __shfl_xor_sync(FULL, fr, 4);
        if (le == 0) {
            float frob = sqrtf(fr);
            sInv[g8] = 1.0f / ((frob > 0.0f) ? frob : 1.0f);
        }

        {
            float q0 = pre0 + pre1;
            float q1 = pre0 * dx0 + pre1 * dx1;
            float q2 = pre0 * dy0 + pre1 * dy1;
            float q3 = pre0 * dz0 + pre1 * dz1;
            float v = bf4(q0, q1, q2, q3, le);
            if (le == 0) sAb[g8] = v;
            else if (le < 4) sBb[g8][le - 1] = v;
        }

        float sk0 = s0, skm0 = 0.0f, cc0 = 2.0f * c0;
        float sk1 = s1, skm1 = 0.0f, cc1 = 2.0f * c1;
        #pragma unroll
        for (int k = 0; k < NRBF; k++) {
            float a0 = pir0 * sk0;
            float a1 = pir1 * sk1;
            float q0 = a0 + a1;
            float q1 = a0 * dx0 + a1 * dx1;
            float q2 = a0 * dy0 + a1 * dy1;
            float q3 = a0 * dz0 + a1 * dz1;
            float v = bf4(q0, q1, q2, q3, le);
            if (le == 0) sA[g8][k] = v;
            else if (le < 4) sB[g8][le - 1][k] = v;
            float sn0 = cc0 * sk0 - skm0; skm0 = sk0; sk0 = sn0;
            float sn1 = cc1 * sk1 - skm1; skm1 = sk1; sk1 = sn1;
        }
    }
    __syncthreads();

    // filter dots per (node, feature)
    {
        int c = t % 3;
        float phi2 = g_phi[S + t];
        float phi3 = g_phi[2 * S + t];
        float fb2 = filt_b[S + t];
        float fb3 = filt_b[2 * S + t];

        ull w2p[NRBF / 2], w3p[NRBF / 2];
        #pragma unroll
        for (int kk = 0; kk < NRBF / 2; kk++) {
            w2p[kk] = pack2(filt_w[(2 * kk) * 3 * S + S + t],
                            filt_w[(2 * kk + 1) * 3 * S + S + t]);
            w3p[kk] = pack2(filt_w[(2 * kk) * 3 * S + 2 * S + t],
                            filt_w[(2 * kk + 1) * 3 * S + 2 * S + t]);
        }
        #pragma unroll
        for (int ni = 0; ni < NPB; ni++) {
            int nn = n0 + ni;
            if (nn >= N) break;
            ull acc2 = 0ull, acc3 = 0ull;
            const ull* pa = (const ull*)&sA[ni][0];
            const ull* pb = (const ull*)&sB[ni][c][0];
            #pragma unroll
            for (int kk = 0; kk < NRBF / 2; kk++) {
                acc2 = ffma2(pa[kk], w2p[kk], acc2);
                acc3 = ffma2(pb[kk], w3p[kk], acc3);
            }
            float a2l, a2h, a3l, a3h;
            unpack2(acc2, a2l, a2h);
            unpack2(acc3, a3l, a3h);
            g_state1[nn * S + t] = phi2 * (a2l + a2h + sAb[ni] * fb2);
            g_vsum[nn * S + t] = phi3 * (a3l + a3h + sBb[ni][c] * fb3) * sInv[ni];
        }
    }
}

// ---------------------------------------------------------------------------
// Kernel 2: per-node MLP + fused graph segment-sum (REDG atomics).
// BN=32 nodes/block, 256 threads (2 halves x 16 nodes).
// ---------------------------------------------------------------------------
__global__ void __launch_bounds__(256) k_node(
        const float* __restrict__ u_w, const float* __restrict__ v_w,
        const float* __restrict__ w1, const float* __restrict__ b1,
        const float* __restrict__ w2, const float* __restrict__ b2,
        const int* __restrict__ gidx, int N) {
    __shared__ __align__(16) float bufA[S * BW];
    __shared__ __align__(16) float bufB[S * BW];
    __shared__ float scp[8][16];
    __shared__ float sc[BN];
    __shared__ int sgidx[BN];

    const unsigned FULL = 0xffffffffu;
    int t = threadIdx.x;
    int f = t & 127;
    int h = t >> 7;
    int colbase = 16 * h;
    int n0 = blockIdx.x * BN;

    if (t < BN) sgidx[t] = gidx[min(n0 + t, N - 1)];

    // fill tiles (each half fills its 16 columns)
    #pragma unroll
    for (int ni = 0; ni < 16; ni++) {
        int col = colbase + ni;
        int nn = min(n0 + col, N - 1);
        bufA[f * BW + col] = g_vsum[nn * S + f];
        bufB[f * BW + col] = g_state1[nn * S + f];
    }
    __syncthreads();

    // U, V matmuls
    ull aU[8], aV[8];
    #pragma unroll
    for (int j = 0; j < 8; j++) { aU[j] = 0ull; aV[j] = 0ull; }
    #pragma unroll 2
    for (int s = 0; s < S; s++) {
        float wu = u_w[s * S + f];
        float wv = v_w[s * S + f];
        ull wuu = pack2(wu, wu), wvv = pack2(wv, wv);
        U4 x0, x1, x2, x3;
        x0.v = *(const float4*)&bufA[s * BW + colbase + 0];
        x1.v = *(const float4*)&bufA[s * BW + colbase + 4];
        x2.v = *(const float4*)&bufA[s * BW + colbase + 8];
        x3.v = *(const float4*)&bufA[s * BW + colbase + 12];
        aU[0] = ffma2(x0.p[0], wuu, aU[0]); aV[0] = ffma2(x0.p[0], wvv, aV[0]);
        aU[1] = ffma2(x0.p[1], wuu, aU[1]); aV[1] = ffma2(x0.p[1], wvv, aV[1]);
        aU[2] = ffma2(x1.p[0], wuu, aU[2]); aV[2] = ffma2(x1.p[0], wvv, aV[2]);
        aU[3] = ffma2(x1.p[1], wuu, aU[3]); aV[3] = ffma2(x1.p[1], wvv, aV[3]);
        aU[4] = ffma2(x2.p[0], wuu, aU[4]); aV[4] = ffma2(x2.p[0], wvv, aV[4]);
        aU[5] = ffma2(x2.p[1], wuu, aU[5]); aV[5] = ffma2(x2.p[1], wvv, aV[5]);
        aU[6] = ffma2(x3.p[0], wuu, aU[6]); aV[6] = ffma2(x3.p[0], wvv, aV[6]);
        aU[7] = ffma2(x3.p[1], wuu, aU[7]); aV[7] = ffma2(x3.p[1], wvv, aV[7]);
    }
    __syncthreads();   // everyone done reading bufA(sv)

    // prod for c[n]; Vnorm into bufA
    const float SQ3 = 1.7320508075688772f;
    float prod[16];
    #pragma unroll
    for (int j = 0; j < 8; j++) {
        float u0, u1, v0, v1;
        unpack2(aU[j], u0, u1);
        unpack2(aV[j], v0, v1);
        prod[2 * j] = u0 * v0;
        prod[2 * j + 1] = u1 * v1;
        bufA[f * BW + colbase + 2 * j] = SQ3 * fabsf(v0);
        bufA[f * BW + colbase + 2 * j + 1] = SQ3 * fabsf(v1);
    }
    int w = t >> 5, lane = t & 31;
    #pragma unroll
    for (int ni = 0; ni < 16; ni++) {
        float v = prod[ni];
        #pragma unroll
        for (int m = 16; m; m >>= 1) v += __shfl_xor_sync(FULL, v, m);
        if (lane == 0) scp[w][ni] = v;
    }
    __syncthreads();
    if (t < BN) {
        int hh = t >> 4, ni = t & 15;
        int wb = hh * 4;
        sc[t] = scp[wb][ni] + scp[wb + 1][ni] + scp[wb + 2][ni] + scp[wb + 3][ni];
    }
    __syncthreads();

    // h = silu([Vnorm, state1] @ upd_w1 + b1)
    ull aH[8];
    #pragma unroll
    for (int j = 0; j < 8; j++) aH[j] = 0ull;
    #pragma unroll 2
    for (int s = 0; s < S; s++) {
        float wA = w1[s * S + f];
        float wB = w1[(S + s) * S + f];
        ull wAA = pack2(wA, wA), wBB = pack2(wB, wB);
        U4 x0, x1, x2, x3, y0, y1, y2, y3;
        x0.v = *(const float4*)&bufA[s * BW + colbase + 0];
        x1.v = *(const float4*)&bufA[s * BW + colbase + 4];
        x2.v = *(const float4*)&bufA[s * BW + colbase + 8];
        x3.v = *(const float4*)&bufA[s * BW + colbase + 12];
        y0.v = *(const float4*)&bufB[s * BW + colbase + 0];
        y1.v = *(const float4*)&bufB[s * BW + colbase + 4];
        y2.v = *(const float4*)&bufB[s * BW + colbase + 8];
        y3.v = *(const float4*)&bufB[s * BW + colbase + 12];
        aH[0] = ffma2(x0.p[0], wAA, aH[0]); aH[0] = ffma2(y0.p[0], wBB, aH[0]);
        aH[1] = ffma2(x0.p[1], wAA, aH[1]); aH[1] = ffma2(y0.p[1], wBB, aH[1]);
        aH[2] = ffma2(x1.p[0], wAA, aH[2]); aH[2] = ffma2(y1.p[0], wBB, aH[2]);
        aH[3] = ffma2(x1.p[1], wAA, aH[3]); aH[3] = ffma2(y1.p[1], wBB, aH[3]);
        aH[4] = ffma2(x2.p[0], wAA, aH[4]); aH[4] = ffma2(y2.p[0], wBB, aH[4]);
        aH[5] = ffma2(x2.p[1], wAA, aH[5]); aH[5] = ffma2(y2.p[1], wBB, aH[5]);
        aH[6] = ffma2(x3.p[0], wAA, aH[6]); aH[6] = ffma2(y3.p[0], wBB, aH[6]);
        aH[7] = ffma2(x3.p[1], wAA, aH[7]); aH[7] = ffma2(y3.p[1], wBB, aH[7]);
    }
    __syncthreads();   // done reading bufA(vn) + bufB(ss)
    {
        float bb = b1[f];
        #pragma unroll
        for (int j = 0; j < 8; j++) {
            float h0, h1v;
            unpack2(aH[j], h0, h1v);
            bufA[f * BW + colbase + 2 * j] = siluf(h0 + bb);
            bufA[f * BW + colbase + 2 * j + 1] = siluf(h1v + bb);
        }
    }
    __syncthreads();

    // a_sv, a_ss; final state -> REDG into graph accumulator
    ull aSV[8], aSS[8];
    #pragma unroll
    for (int j = 0; j < 8; j++) { aSV[j] = 0ull; aSS[j] = 0ull; }
    #pragma unroll 2
    for (int s = 0; s < S; s++) {
        float wsv = w2[s * 3 * S + S + f];
        float wss = w2[s * 3 * S + 2 * S + f];
        ull wv2 = pack2(wsv, wsv), ws2 = pack2(wss, wss);
        U4 x0, x1, x2, x3;
        x0.v = *(const float4*)&bufA[s * BW + colbase + 0];
        x1.v = *(const float4*)&bufA[s * BW + colbase + 4];
        x2.v = *(const float4*)&bufA[s * BW + colbase + 8];
        x3.v = *(const float4*)&bufA[s * BW + colbase + 12];
        aSV[0] = ffma2(x0.p[0], wv2, aSV[0]); aSS[0] = ffma2(x0.p[0], ws2, aSS[0]);
        aSV[1] = ffma2(x0.p[1], wv2, aSV[1]); aSS[1] = ffma2(x0.p[1], ws2, aSS[1]);
        aSV[2] = ffma2(x1.p[0], wv2, aSV[2]); aSS[2] = ffma2(x1.p[0], ws2, aSS[2]);
        aSV[3] = ffma2(x1.p[1], wv2, aSV[3]); aSS[3] = ffma2(x1.p[1], ws2, aSS[3]);
        aSV[4] = ffma2(x2.p[0], wv2, aSV[4]); aSS[4] = ffma2(x2.p[0], ws2, aSS[4]);
        aSV[5] = ffma2(x2.p[1], wv2, aSV[5]); aSS[5] = ffma2(x2.p[1], ws2, aSS[5]);
        aSV[6] = ffma2(x3.p[0], wv2, aSV[6]); aSS[6] = ffma2(x3.p[0], ws2, aSS[6]);
        aSV[7] = ffma2(x3.p[1], wv2, aSV[7]); aSS[7] = ffma2(x3.p[1], ws2, aSS[7]);
    }
    {
        float bsv = b2[S + f];
        float bss = b2[2 * S + f];
        #pragma unroll
        for (int j = 0; j < 8; j++) {
            float sv0, sv1, ss0, ss1;
            unpack2(aSV[j], sv0, sv1);
            unpack2(aSS[j], ss0, ss1);
            int col = colbase + 2 * j;
            int nn0 = n0 + col;
            if (nn0 < N) {
                float v = (ss0 + bss) + 3.0f * sc[col] * (sv0 + bsv);
                atomicAdd(&g_graph[sgidx[col] * S + f], v);
            }
            if (nn0 + 1 < N) {
                float v = (ss1 + bss) + 3.0f * sc[col + 1] * (sv1 + bsv);
                atomicAdd(&g_graph[sgidx[col + 1] * S + f], v);
            }
        }
    }
}

// ---------------------------------------------------------------------------
// Output MLP per graph
// ---------------------------------------------------------------------------
__global__ void k_out(const float* __restrict__ w1, const float* __restrict__ b1,
                      const float* __restrict__ w2, const float* __restrict__ b2,
                      float* __restrict__ out) {
    __shared__ float gs[S];
    __shared__ float red[4];
    int g = blockIdx.x, t = threadIdx.x;
    gs[t] = g_graph[g * S + t];
    __syncthreads();
    float hacc = b1[t];
    #pragma unroll 4
    for (int s = 0; s < S; s++) hacc += gs[s] * w1[s * S + t];
    float h = hacc / (1.0f + expf(-hacc));
    float p = h * w2[t];
    #pragma unroll
    for (int m = 16; m; m >>= 1) p += __shfl_xor_sync(0xffffffffu, p, m);
    int w = t >> 5, lane = t & 31;
    if (lane == 0) red[w] = p;
    __syncthreads();
    if (t == 0) out[g] = red[0] + red[1] + red[2] + red[3] + b2[0];
}

// ---------------------------------------------------------------------------
extern "C" void kernel_launch(void* const* d_in, const int* in_sizes, int n_in,
                              void* d_out, int out_size) {
    int N = in_sizes[3];
    int off = (n_in >= 22) ? 1 : 0;

    const float* diffs   = (const float*)d_in[0];
    const float* lens    = (const float*)d_in[1];
    const int*   gidx    = (const int*)d_in[3];
    const float* emb0    = (const float*)d_in[4 + off];
    const float* phi_w1  = (const float*)d_in[5 + off];
    const float* phi_b1  = (const float*)d_in[6 + off];
    const float* phi_w2  = (const float*)d_in[7 + off];
    const float* phi_b2  = (const float*)d_in[8 + off];
    const float* filt_w  = (const float*)d_in[9 + off];
    const float* filt_b  = (const float*)d_in[10 + off];
    const float* u_w     = (const float*)d_in[11 + off];
    const float* v_w     = (const float*)d_in[12 + off];
    const float* upd_w1  = (const float*)d_in[13 + off];
    const float* upd_b1  = (const float*)d_in[14 + off];
    const float* upd_w2  = (const float*)d_in[15 + off];
    const float* upd_b2  = (const float*)d_in[16 + off];
    const float* out_w1  = (const float*)d_in[17 + off];
    const float* out_b1  = (const float*)d_in[18 + off];
    const float* out_w2  = (const float*)d_in[19 + off];
    const float* out_b2  = (const float*)d_in[20 + off];
    float* out = (float*)d_out;
    int G = out_size;

    k_phi<<<1, 3 * S>>>(emb0, phi_w1, phi_b1, phi_w2, phi_b2);

    int nblk1 = (N + NPB - 1) / NPB;
    k_edge<<<nblk1, 128>>>(diffs, lens, filt_w, filt_b, N);

    int nblk2 = (N + BN - 1) / BN;
    k_node<<<nblk2, 256>>>(u_w, v_w, upd_w1, upd_b1, upd_w2, upd_b2, gidx, N);

    k_out<<<G, 128>>>(out_w1, out_b1, out_w2, out_b2, out);
}

// round 6
// speedup vs baseline: 1.5641x; 1.2116x over previous
#include <cuda_runtime.h>
#include <math.h>

#define S 128
#define NRBF 20
#define DEG 16
#define NPB 16        // nodes per block in k_edge
#define BN 36         // nodes per block in k_node (278 blocks = 1 wave @ 2/SM)
#define NCOL 18       // columns per 128-thread half
#define NACC 9        // f32x2 accumulators per half
#define BW 42         // padded tile width (8B-aligned halves, 2-way store conflicts)
#define GMAX 64

__device__ float g_phi[3 * S];
__device__ float g_state1[10240 * S];
__device__ float g_vsum[10240 * S];
__device__ float g_graph[GMAX * S];

typedef unsigned long long ull;

__device__ __forceinline__ float siluf(float x) {
    return x / (1.0f + expf(-x));
}
__device__ __forceinline__ ull pack2(float a, float b) {
    ull r;
    asm("mov.b64 %0, {%1,%2};" : "=l"(r) : "f"(a), "f"(b));
    return r;
}
__device__ __forceinline__ ull ffma2(ull a, ull b, ull c) {
    ull d;
    asm("fma.rn.f32x2 %0, %1, %2, %3;" : "=l"(d) : "l"(a), "l"(b), "l"(c));
    return d;
}
__device__ __forceinline__ void unpack2(ull p, float& lo, float& hi) {
    asm("mov.b64 {%0,%1}, %2;" : "=f"(lo), "=f"(hi) : "l"(p));
}

// 4-channel butterfly over 8-lane groups
__device__ __forceinline__ float bf4(float q0, float q1, float q2, float q3, int le) {
    const unsigned FULL = 0xffffffffu;
    float a = (le & 1) ? q1 : q0;
    float b = (le & 1) ? q0 : q1;
    a += __shfl_xor_sync(FULL, b, 1);
    float c = (le & 1) ? q3 : q2;
    float d = (le & 1) ? q2 : q3;
    c += __shfl_xor_sync(FULL, d, 1);
    float e = (le & 2) ? c : a;
    float f = (le & 2) ? a : c;
    e += __shfl_xor_sync(FULL, f, 2);
    e += __shfl_xor_sync(FULL, e, 4);
    return e;
}

// ---------------------------------------------------------------------------
// Kernel 0: phi vector + zero graph accumulator
// ---------------------------------------------------------------------------
__global__ void k_phi(const float* __restrict__ emb0,
                      const float* __restrict__ w1, const float* __restrict__ b1,
                      const float* __restrict__ w2, const float* __restrict__ b2) {
    __shared__ float h1[S];
    int t = threadIdx.x;
    for (int i = t; i < GMAX * S; i += 384) g_graph[i] = 0.0f;
    if (t < S) {
        float acc = b1[t];
        #pragma unroll 4
        for (int s = 0; s < S; s++)
            acc += (128.0f * emb0[s]) * w1[s * S + t];
        h1[t] = siluf(acc);
    }
    __syncthreads();
    if (t < 3 * S) {
        float acc = b2[t];
        #pragma unroll 4
        for (int j = 0; j < S; j++)
            acc += h1[j] * w2[j * 3 * S + t];
        g_phi[t] = acc;
    }
}

// ---------------------------------------------------------------------------
// Kernel 1: edge statistics + filter dots -> g_state1, g_vsum.
// ---------------------------------------------------------------------------
__global__ void __launch_bounds__(128) k_edge(
        const float* __restrict__ diffs, const float* __restrict__ lens,
        const float* __restrict__ filt_w, const float* __restrict__ filt_b,
        int N) {
    __shared__ __align__(16) float sA[NPB][NRBF];
    __shared__ __align__(16) float sB[NPB][3][NRBF];
    __shared__ float sAb[NPB];
    __shared__ float sBb[NPB][3];
    __shared__ float sInv[NPB];

    const unsigned FULL = 0xffffffffu;
    int t = threadIdx.x;
    int n0 = blockIdx.x * NPB;

    {
        int g8 = t >> 3;
        int le = t & 7;
        int nc = min(n0 + g8, N - 1);
        int e0 = nc * DEG + le * 2;

        float dx0 = diffs[3 * e0 + 0], dy0 = diffs[3 * e0 + 1], dz0 = diffs[3 * e0 + 2];
        float dx1 = diffs[3 * e0 + 3], dy1 = diffs[3 * e0 + 4], dz1 = diffs[3 * e0 + 5];
        float l0 = lens[e0], l1 = lens[e0 + 1];

        float r20 = dx0 * dx0 + dy0 * dy0 + dz0 * dz0;
        float r21 = dx1 * dx1 + dy1 * dy1 + dz1 * dz1;
        float r0 = sqrtf(r20), r1 = sqrtf(r21);
        float m0 = (fabsf(l0) <= 10.0f) ? 1.0f : 0.0f;
        float m1 = (fabsf(l1) <= 10.0f) ? 1.0f : 0.0f;
        float rs0 = fmaxf(r0, 1e-12f), rs1 = fmaxf(r1, 1e-12f);
        float b0 = rs0 * 0.1f, b1e = rs1 * 0.1f;
        float c0 = cospif(b0), c1 = cospif(b1e);
        float s0 = sinpif(b0), s1 = sinpif(b1e);
        float cut0 = (r0 < 10.0f) ? 0.5f * (c0 + 1.0f) : 0.0f;
        float cut1 = (r1 < 10.0f) ? 0.5f * (c1 + 1.0f) : 0.0f;
        float pir0 = m0 * cut0 / rs0;
        float pir1 = m1 * cut1 / rs1;
        float pre0 = m0 * cut0, pre1 = m1 * cut1;

        float fr = m0 * r20 + m1 * r21;
        fr += __shfl_xor_sync(FULL, fr, 1);
        fr += __shfl_xor_sync(FULL, fr, 2);
        fr += __shfl_xor_sync(FULL, fr, 4);
        if (le == 0) {
            float frob = sqrtf(fr);
            sInv[g8] = 1.0f / ((frob > 0.0f) ? frob : 1.0f);
        }

        {
            float q0 = pre0 + pre1;
            float q1 = pre0 * dx0 + pre1 * dx1;
            float q2 = pre0 * dy0 + pre1 * dy1;
            float q3 = pre0 * dz0 + pre1 * dz1;
            float v = bf4(q0, q1, q2, q3, le);
            if (le == 0) sAb[g8] = v;
            else if (le < 4) sBb[g8][le - 1] = v;
        }

        float sk0 = s0, skm0 = 0.0f, cc0 = 2.0f * c0;
        float sk1 = s1, skm1 = 0.0f, cc1 = 2.0f * c1;
        #pragma unroll
        for (int k = 0; k < NRBF; k++) {
            float a0 = pir0 * sk0;
            float a1 = pir1 * sk1;
            float q0 = a0 + a1;
            float q1 = a0 * dx0 + a1 * dx1;
            float q2 = a0 * dy0 + a1 * dy1;
            float q3 = a0 * dz0 + a1 * dz1;
            float v = bf4(q0, q1, q2, q3, le);
            if (le == 0) sA[g8][k] = v;
            else if (le < 4) sB[g8][le - 1][k] = v;
            float sn0 = cc0 * sk0 - skm0; skm0 = sk0; sk0 = sn0;
            float sn1 = cc1 * sk1 - skm1; skm1 = sk1; sk1 = sn1;
        }
    }
    __syncthreads();

    {
        int c = t % 3;
        float phi2 = g_phi[S + t];
        float phi3 = g_phi[2 * S + t];
        float fb2 = filt_b[S + t];
        float fb3 = filt_b[2 * S + t];

        ull w2p[NRBF / 2], w3p[NRBF / 2];
        #pragma unroll
        for (int kk = 0; kk < NRBF / 2; kk++) {
            w2p[kk] = pack2(filt_w[(2 * kk) * 3 * S + S + t],
                            filt_w[(2 * kk + 1) * 3 * S + S + t]);
            w3p[kk] = pack2(filt_w[(2 * kk) * 3 * S + 2 * S + t],
                            filt_w[(2 * kk + 1) * 3 * S + 2 * S + t]);
        }
        #pragma unroll
        for (int ni = 0; ni < NPB; ni++) {
            int nn = n0 + ni;
            if (nn >= N) break;
            ull acc2 = 0ull, acc3 = 0ull;
            const ull* pa = (const ull*)&sA[ni][0];
            const ull* pb = (const ull*)&sB[ni][c][0];
            #pragma unroll
            for (int kk = 0; kk < NRBF / 2; kk++) {
                acc2 = ffma2(pa[kk], w2p[kk], acc2);
                acc3 = ffma2(pb[kk], w3p[kk], acc3);
            }
            float a2l, a2h, a3l, a3h;
            unpack2(acc2, a2l, a2h);
            unpack2(acc3, a3l, a3h);
            g_state1[nn * S + t] = phi2 * (a2l + a2h + sAb[ni] * fb2);
            g_vsum[nn * S + t] = phi3 * (a3l + a3h + sBb[ni][c] * fb3) * sInv[ni];
        }
    }
}

// ---------------------------------------------------------------------------
// Kernel 2: per-node MLP + fused graph segment-sum (REDG atomics).
// BN=36 nodes/block, 256 threads = 2 halves x 18 columns.
// ---------------------------------------------------------------------------
__global__ void __launch_bounds__(256, 2) k_node(
        const float* __restrict__ u_w, const float* __restrict__ v_w,
        const float* __restrict__ w1, const float* __restrict__ b1,
        const float* __restrict__ w2, const float* __restrict__ b2,
        const int* __restrict__ gidx, int N) {
    __shared__ __align__(16) float bufA[S * BW];
    __shared__ __align__(16) float bufB[S * BW];
    __shared__ float scp[8][NCOL];
    __shared__ float sc[BN];
    __shared__ int sgidx[BN];

    const unsigned FULL = 0xffffffffu;
    int t = threadIdx.x;
    int f = t & 127;
    int h = t >> 7;
    int colbase = NCOL * h;
    int n0 = blockIdx.x * BN;

    if (t < BN) sgidx[t] = gidx[min(n0 + t, N - 1)];

    #pragma unroll
    for (int ni = 0; ni < NCOL; ni++) {
        int col = colbase + ni;
        int nn = min(n0 + col, N - 1);
        bufA[f * BW + col] = g_vsum[nn * S + f];
        bufB[f * BW + col] = g_state1[nn * S + f];
    }
    __syncthreads();

    // U, V matmuls
    ull aU[NACC], aV[NACC];
    #pragma unroll
    for (int j = 0; j < NACC; j++) { aU[j] = 0ull; aV[j] = 0ull; }
    #pragma unroll 2
    for (int s = 0; s < S; s++) {
        float wu = u_w[s * S + f];
        float wv = v_w[s * S + f];
        ull wuu = pack2(wu, wu), wvv = pack2(wv, wv);
        const ull* row = (const ull*)&bufA[s * BW + colbase];
        #pragma unroll
        for (int j = 0; j < NACC; j++) {
            ull x = row[j];
            aU[j] = ffma2(x, wuu, aU[j]);
            aV[j] = ffma2(x, wvv, aV[j]);
        }
    }
    __syncthreads();   // done reading bufA(sv)

    // prod for c[n]; Vnorm into bufA
    const float SQ3 = 1.7320508075688772f;
    float prod[NCOL];
    #pragma unroll
    for (int j = 0; j < NACC; j++) {
        float u0, u1, v0, v1;
        unpack2(aU[j], u0, u1);
        unpack2(aV[j], v0, v1);
        prod[2 * j] = u0 * v0;
        prod[2 * j + 1] = u1 * v1;
        bufA[f * BW + colbase + 2 * j] = SQ3 * fabsf(v0);
        bufA[f * BW + colbase + 2 * j + 1] = SQ3 * fabsf(v1);
    }
    int w = t >> 5, lane = t & 31;
    #pragma unroll
    for (int ni = 0; ni < NCOL; ni++) {
        float v = prod[ni];
        #pragma unroll
        for (int m = 16; m; m >>= 1) v += __shfl_xor_sync(FULL, v, m);
        if (lane == 0) scp[w][ni] = v;
    }
    __syncthreads();
    if (t < BN) {
        int hh = t / NCOL, ni = t % NCOL;
        int wb = hh * 4;
        sc[t] = scp[wb][ni] + scp[wb + 1][ni] + scp[wb + 2][ni] + scp[wb + 3][ni];
    }
    __syncthreads();

    // h = silu([Vnorm, state1] @ upd_w1 + b1)
    ull aH[NACC];
    #pragma unroll
    for (int j = 0; j < NACC; j++) aH[j] = 0ull;
    #pragma unroll 2
    for (int s = 0; s < S; s++) {
        float wA = w1[s * S + f];
        float wB = w1[(S + s) * S + f];
        ull wAA = pack2(wA, wA), wBB = pack2(wB, wB);
        const ull* rowA = (const ull*)&bufA[s * BW + colbase];
        const ull* rowB = (const ull*)&bufB[s * BW + colbase];
        #pragma unroll
        for (int j = 0; j < NACC; j++) {
            aH[j] = ffma2(rowA[j], wAA, aH[j]);
            aH[j] = ffma2(rowB[j], wBB, aH[j]);
        }
    }
    __syncthreads();   // done reading bufA(vn) + bufB(ss)
    {
        float bb = b1[f];
        #pragma unroll
        for (int j = 0; j < NACC; j++) {
            float h0, h1v;
            unpack2(aH[j], h0, h1v);
            bufA[f * BW + colbase + 2 * j] = siluf(h0 + bb);
            bufA[f * BW + colbase + 2 * j + 1] = siluf(h1v + bb);
        }
    }
    __syncthreads();

    // a_sv, a_ss; final state -> REDG into graph accumulator
    ull aSV[NACC], aSS[NACC];
    #pragma unroll
    for (int j = 0; j < NACC; j++) { aSV[j] = 0ull; aSS[j] = 0ull; }
    #pragma unroll 2
    for (int s = 0; s < S; s++) {
        float wsv = w2[s * 3 * S + S + f];
        float wss = w2[s * 3 * S + 2 * S + f];
        ull wv2 = pack2(wsv, wsv), ws2 = pack2(wss, wss);
        const ull* row = (const ull*)&bufA[s * BW + colbase];
        #pragma unroll
        for (int j = 0; j < NACC; j++) {
            ull x = row[j];
            aSV[j] = ffma2(x, wv2, aSV[j]);
            aSS[j] = ffma2(x, ws2, aSS[j]);
        }
    }
    {
        float bsv = b2[S + f];
        float bss = b2[2 * S + f];
        #pragma unroll
        for (int j = 0; j < NACC; j++) {
            float sv0, sv1, ss0, ss1;
            unpack2(aSV[j], sv0, sv1);
            unpack2(aSS[j], ss0, ss1);
            int col = colbase + 2 * j;
            int nn0 = n0 + col;
            if (nn0 < N) {
                float v = (ss0 + bss) + 3.0f * sc[col] * (sv0 + bsv);
                atomicAdd(&g_graph[sgidx[col] * S + f], v);
            }
            if (nn0 + 1 < N) {
                float v = (ss1 + bss) + 3.0f * sc[col + 1] * (sv1 + bsv);
                atomicAdd(&g_graph[sgidx[col + 1] * S + f], v);
            }
        }
    }
}

// ---------------------------------------------------------------------------
// Output MLP per graph: 4 independent accumulator chains, full unroll
// ---------------------------------------------------------------------------
__global__ void __launch_bounds__(128) k_out(
        const float* __restrict__ w1, const float* __restrict__ b1,
        const float* __restrict__ w2, const float* __restrict__ b2,
        float* __restrict__ out) {
    __shared__ float gs[S];
    __shared__ float red[4];
    int g = blockIdx.x, t = threadIdx.x;
    gs[t] = g_graph[g * S + t];
    __syncthreads();
    float a0 = b1[t], a1 = 0.0f, a2 = 0.0f, a3 = 0.0f;
    #pragma unroll
    for (int s = 0; s < S; s += 4) {
        a0 += gs[s + 0] * w1[(s + 0) * S + t];
        a1 += gs[s + 1] * w1[(s + 1) * S + t];
        a2 += gs[s + 2] * w1[(s + 2) * S + t];
        a3 += gs[s + 3] * w1[(s + 3) * S + t];
    }
    float hacc = (a0 + a1) + (a2 + a3);
    float h = hacc / (1.0f + expf(-hacc));
    float p = h * w2[t];
    #pragma unroll
    for (int m = 16; m; m >>= 1) p += __shfl_xor_sync(0xffffffffu, p, m);
    int w = t >> 5, lane = t & 31;
    if (lane == 0) red[w] = p;
    __syncthreads();
    if (t == 0) out[g] = red[0] + red[1] + red[2] + red[3] + b2[0];
}

// ---------------------------------------------------------------------------
extern "C" void kernel_launch(void* const* d_in, const int* in_sizes, int n_in,
                              void* d_out, int out_size) {
    int N = in_sizes[3];
    int off = (n_in >= 22) ? 1 : 0;

    const float* diffs   = (const float*)d_in[0];
    const float* lens    = (const float*)d_in[1];
    const int*   gidx    = (const int*)d_in[3];
    const float* emb0    = (const float*)d_in[4 + off];
    const float* phi_w1  = (const float*)d_in[5 + off];
    const float* phi_b1  = (const float*)d_in[6 + off];
    const float* phi_w2  = (const float*)d_in[7 + off];
    const float* phi_b2  = (const float*)d_in[8 + off];
    const float* filt_w  = (const float*)d_in[9 + off];
    const float* filt_b  = (const float*)d_in[10 + off];
    const float* u_w     = (const float*)d_in[11 + off];
    const float* v_w     = (const float*)d_in[12 + off];
    const float* upd_w1  = (const float*)d_in[13 + off];
    const float* upd_b1  = (const float*)d_in[14 + off];
    const float* upd_w2  = (const float*)d_in[15 + off];
    const float* upd_b2  = (const float*)d_in[16 + off];
    const float* out_w1  = (const float*)d_in[17 + off];
    const float* out_b1  = (const float*)d_in[18 + off];
    const float* out_w2  = (const float*)d_in[19 + off];
    const float* out_b2  = (const float*)d_in[20 + off];
    float* out = (float*)d_out;
    int G = out_size;

    k_phi<<<1, 3 * S>>>(emb0, phi_w1, phi_b1, phi_w2, phi_b2);

    int nblk1 = (N + NPB - 1) / NPB;
    k_edge<<<nblk1, 128>>>(diffs, lens, filt_w, filt_b, N);

    int nblk2 = (N + BN - 1) / BN;
    k_node<<<nblk2, 256>>>(u_w, v_w, upd_w1, upd_b1, upd_w2, upd_b2, gidx, N);

    k_out<<<G, 128>>>(out_w1, out_b1, out_w2, out_b2, out);
}

// round 7
// speedup vs baseline: 1.6111x; 1.0300x over previous
#include <cuda_runtime.h>
#include <math.h>

#define S 128
#define NRBF 20
#define DEG 16
#define NPB 32        // nodes per block in k_edge (256 threads)
#define BN 36         // nodes per block in k_node (278 blocks = 1 wave @ 2/SM)
#define NCOL 18       // columns per 128-thread half
#define NACC 9        // f32x2 accumulators per half
#define BW 42         // padded tile width
#define GMAX 64

__device__ float g_phi[3 * S];
__device__ float g_state1[10240 * S];
__device__ float g_vsum[10240 * S];
__device__ float g_graph[GMAX * S];

typedef unsigned long long ull;

__device__ __forceinline__ float siluf(float x) {
    return x / (1.0f + expf(-x));
}
__device__ __forceinline__ ull pack2(float a, float b) {
    ull r;
    asm("mov.b64 %0, {%1,%2};" : "=l"(r) : "f"(a), "f"(b));
    return r;
}
__device__ __forceinline__ ull ffma2(ull a, ull b, ull c) {
    ull d;
    asm("fma.rn.f32x2 %0, %1, %2, %3;" : "=l"(d) : "l"(a), "l"(b), "l"(c));
    return d;
}
__device__ __forceinline__ void unpack2(ull p, float& lo, float& hi) {
    asm("mov.b64 {%0,%1}, %2;" : "=f"(lo), "=f"(hi) : "l"(p));
}

// 4-channel butterfly over 8-lane groups
__device__ __forceinline__ float bf4(float q0, float q1, float q2, float q3, int le) {
    const unsigned FULL = 0xffffffffu;
    float a = (le & 1) ? q1 : q0;
    float b = (le & 1) ? q0 : q1;
    a += __shfl_xor_sync(FULL, b, 1);
    float c = (le & 1) ? q3 : q2;
    float d = (le & 1) ? q2 : q3;
    c += __shfl_xor_sync(FULL, d, 1);
    float e = (le & 2) ? c : a;
    float f = (le & 2) ? a : c;
    e += __shfl_xor_sync(FULL, f, 2);
    e += __shfl_xor_sync(FULL, e, 4);
    return e;
}

// ---------------------------------------------------------------------------
// Kernel 0: phi vector + zero graph accumulator (ILP'd)
// ---------------------------------------------------------------------------
__global__ void k_phi(const float* __restrict__ emb0,
                      const float* __restrict__ w1, const float* __restrict__ b1,
                      const float* __restrict__ w2, const float* __restrict__ b2) {
    __shared__ float h1[S];
    int t = threadIdx.x;
    for (int i = t; i < GMAX * S; i += 384) g_graph[i] = 0.0f;
    if (t < S) {
        float a0 = b1[t], a1 = 0.0f, a2 = 0.0f, a3 = 0.0f;
        #pragma unroll
        for (int s = 0; s < S; s += 4) {
            a0 += (128.0f * emb0[s + 0]) * w1[(s + 0) * S + t];
            a1 += (128.0f * emb0[s + 1]) * w1[(s + 1) * S + t];
            a2 += (128.0f * emb0[s + 2]) * w1[(s + 2) * S + t];
            a3 += (128.0f * emb0[s + 3]) * w1[(s + 3) * S + t];
        }
        float acc = (a0 + a1) + (a2 + a3);
        h1[t] = siluf(acc);
    }
    __syncthreads();
    if (t < 3 * S) {
        float a0 = b2[t], a1 = 0.0f, a2 = 0.0f, a3 = 0.0f;
        #pragma unroll
        for (int j = 0; j < S; j += 4) {
            a0 += h1[j + 0] * w2[(j + 0) * 3 * S + t];
            a1 += h1[j + 1] * w2[(j + 1) * 3 * S + t];
            a2 += h1[j + 2] * w2[(j + 2) * 3 * S + t];
            a3 += h1[j + 3] * w2[(j + 3) * 3 * S + t];
        }
        g_phi[t] = (a0 + a1) + (a2 + a3);
    }
}

// ---------------------------------------------------------------------------
// Kernel 1: edge statistics + filter dots. 32 nodes/block, 256 threads.
// ---------------------------------------------------------------------------
__global__ void __launch_bounds__(256) k_edge(
        const float* __restrict__ diffs, const float* __restrict__ lens,
        const float* __restrict__ filt_w, const float* __restrict__ filt_b,
        int N) {
    __shared__ __align__(16) float sA[NPB][NRBF];
    __shared__ __align__(16) float sB[NPB][3][NRBF];
    __shared__ float sAb[NPB];
    __shared__ float sBb[NPB][3];
    __shared__ float sInv[NPB];

    const unsigned FULL = 0xffffffffu;
    int t = threadIdx.x;
    int n0 = blockIdx.x * NPB;

    {
        int g8 = t >> 3;
        int le = t & 7;
        int nc = min(n0 + g8, N - 1);
        int e0 = nc * DEG + le * 2;

        float dx0 = diffs[3 * e0 + 0], dy0 = diffs[3 * e0 + 1], dz0 = diffs[3 * e0 + 2];
        float dx1 = diffs[3 * e0 + 3], dy1 = diffs[3 * e0 + 4], dz1 = diffs[3 * e0 + 5];
        float l0 = lens[e0], l1 = lens[e0 + 1];

        float r20 = dx0 * dx0 + dy0 * dy0 + dz0 * dz0;
        float r21 = dx1 * dx1 + dy1 * dy1 + dz1 * dz1;
        float r0 = sqrtf(r20), r1 = sqrtf(r21);
        float m0 = (fabsf(l0) <= 10.0f) ? 1.0f : 0.0f;
        float m1 = (fabsf(l1) <= 10.0f) ? 1.0f : 0.0f;
        float rs0 = fmaxf(r0, 1e-12f), rs1 = fmaxf(r1, 1e-12f);
        float b0 = rs0 * 0.1f, b1e = rs1 * 0.1f;
        float c0 = cospif(b0), c1 = cospif(b1e);
        float s0 = sinpif(b0), s1 = sinpif(b1e);
        float cut0 = (r0 < 10.0f) ? 0.5f * (c0 + 1.0f) : 0.0f;
        float cut1 = (r1 < 10.0f) ? 0.5f * (c1 + 1.0f) : 0.0f;
        float pir0 = m0 * cut0 / rs0;
        float pir1 = m1 * cut1 / rs1;
        float pre0 = m0 * cut0, pre1 = m1 * cut1;

        float fr = m0 * r20 + m1 * r21;
        fr += __shfl_xor_sync(FULL, fr, 1);
        fr += __shfl_xor_sync(FULL, fr, 2);
        fr += __shfl_xor_sync(FULL, fr, 4);
        if (le == 0) {
            float frob = sqrtf(fr);
            sInv[g8] = 1.0f / ((frob > 0.0f) ? frob : 1.0f);
        }

        {
            float q0 = pre0 + pre1;
            float q1 = pre0 * dx0 + pre1 * dx1;
            float q2 = pre0 * dy0 + pre1 * dy1;
            float q3 = pre0 * dz0 + pre1 * dz1;
            float v = bf4(q0, q1, q2, q3, le);
            if (le == 0) sAb[g8] = v;
            else if (le < 4) sBb[g8][le - 1] = v;
        }

        float sk0 = s0, skm0 = 0.0f, cc0 = 2.0f * c0;
        float sk1 = s1, skm1 = 0.0f, cc1 = 2.0f * c1;
        #pragma unroll
        for (int k = 0; k < NRBF; k++) {
            float a0 = pir0 * sk0;
            float a1 = pir1 * sk1;
            float q0 = a0 + a1;
            float q1 = a0 * dx0 + a1 * dx1;
            float q2 = a0 * dy0 + a1 * dy1;
            float q3 = a0 * dz0 + a1 * dz1;
            float v = bf4(q0, q1, q2, q3, le);
            if (le == 0) sA[g8][k] = v;
            else if (le < 4) sB[g8][le - 1][k] = v;
            float sn0 = cc0 * sk0 - skm0; skm0 = sk0; sk0 = sn0;
            float sn1 = cc1 * sk1 - skm1; skm1 = sk1; sk1 = sn1;
        }
    }
    __syncthreads();

    // Phase 2: each 128-thread half handles 16 nodes
    {
        int f = t & 127;
        int h = t >> 7;
        int nbase = h * 16;
        int c = f % 3;
        float phi2 = g_phi[S + f];
        float phi3 = g_phi[2 * S + f];
        float fb2 = filt_b[S + f];
        float fb3 = filt_b[2 * S + f];

        ull w2p[NRBF / 2], w3p[NRBF / 2];
        #pragma unroll
        for (int kk = 0; kk < NRBF / 2; kk++) {
            w2p[kk] = pack2(filt_w[(2 * kk) * 3 * S + S + f],
                            filt_w[(2 * kk + 1) * 3 * S + S + f]);
            w3p[kk] = pack2(filt_w[(2 * kk) * 3 * S + 2 * S + f],
                            filt_w[(2 * kk + 1) * 3 * S + 2 * S + f]);
        }
        #pragma unroll
        for (int ni0 = 0; ni0 < 16; ni0++) {
            int ni = nbase + ni0;
            int nn = n0 + ni;
            if (nn >= N) break;
            ull acc2 = 0ull, acc3 = 0ull;
            const ull* pa = (const ull*)&sA[ni][0];
            const ull* pb = (const ull*)&sB[ni][c][0];
            #pragma unroll
            for (int kk = 0; kk < NRBF / 2; kk++) {
                acc2 = ffma2(pa[kk], w2p[kk], acc2);
                acc3 = ffma2(pb[kk], w3p[kk], acc3);
            }
            float a2l, a2h, a3l, a3h;
            unpack2(acc2, a2l, a2h);
            unpack2(acc3, a3l, a3h);
            g_state1[nn * S + f] = phi2 * (a2l + a2h + sAb[ni] * fb2);
            g_vsum[nn * S + f] = phi3 * (a3l + a3h + sBb[ni][c] * fb3) * sInv[ni];
        }
    }
}

// ---------------------------------------------------------------------------
// Kernel 2: per-node MLP + fused graph segment-sum (REDG atomics).
// BN=36 nodes/block, 256 threads = 2 halves x 18 columns.  (frozen from R6)
// ---------------------------------------------------------------------------
__global__ void __launch_bounds__(256, 2) k_node(
        const float* __restrict__ u_w, const float* __restrict__ v_w,
        const float* __restrict__ w1, const float* __restrict__ b1,
        const float* __restrict__ w2, const float* __restrict__ b2,
        const int* __restrict__ gidx, int N) {
    __shared__ __align__(16) float bufA[S * BW];
    __shared__ __align__(16) float bufB[S * BW];
    __shared__ float scp[8][NCOL];
    __shared__ float sc[BN];
    __shared__ int sgidx[BN];

    const unsigned FULL = 0xffffffffu;
    int t = threadIdx.x;
    int f = t & 127;
    int h = t >> 7;
    int colbase = NCOL * h;
    int n0 = blockIdx.x * BN;

    if (t < BN) sgidx[t] = gidx[min(n0 + t, N - 1)];

    #pragma unroll
    for (int ni = 0; ni < NCOL; ni++) {
        int col = colbase + ni;
        int nn = min(n0 + col, N - 1);
        bufA[f * BW + col] = g_vsum[nn * S + f];
        bufB[f * BW + col] = g_state1[nn * S + f];
    }
    __syncthreads();

    // U, V matmuls
    ull aU[NACC], aV[NACC];
    #pragma unroll
    for (int j = 0; j < NACC; j++) { aU[j] = 0ull; aV[j] = 0ull; }
    #pragma unroll 2
    for (int s = 0; s < S; s++) {
        float wu = u_w[s * S + f];
        float wv = v_w[s * S + f];
        ull wuu = pack2(wu, wu), wvv = pack2(wv, wv);
        const ull* row = (const ull*)&bufA[s * BW + colbase];
        #pragma unroll
        for (int j = 0; j < NACC; j++) {
            ull x = row[j];
            aU[j] = ffma2(x, wuu, aU[j]);
            aV[j] = ffma2(x, wvv, aV[j]);
        }
    }
    __syncthreads();

    const float SQ3 = 1.7320508075688772f;
    float prod[NCOL];
    #pragma unroll
    for (int j = 0; j < NACC; j++) {
        float u0, u1, v0, v1;
        unpack2(aU[j], u0, u1);
        unpack2(aV[j], v0, v1);
        prod[2 * j] = u0 * v0;
        prod[2 * j + 1] = u1 * v1;
        bufA[f * BW + colbase + 2 * j] = SQ3 * fabsf(v0);
        bufA[f * BW + colbase + 2 * j + 1] = SQ3 * fabsf(v1);
    }
    int w = t >> 5, lane = t & 31;
    #pragma unroll
    for (int ni = 0; ni < NCOL; ni++) {
        float v = prod[ni];
        #pragma unroll
        for (int m = 16; m; m >>= 1) v += __shfl_xor_sync(FULL, v, m);
        if (lane == 0) scp[w][ni] = v;
    }
    __syncthreads();
    if (t < BN) {
        int hh = t / NCOL, ni = t % NCOL;
        int wb = hh * 4;
        sc[t] = scp[wb][ni] + scp[wb + 1][ni] + scp[wb + 2][ni] + scp[wb + 3][ni];
    }
    __syncthreads();

    // h = silu([Vnorm, state1] @ upd_w1 + b1)
    ull aH[NACC];
    #pragma unroll
    for (int j = 0; j < NACC; j++) aH[j] = 0ull;
    #pragma unroll 2
    for (int s = 0; s < S; s++) {
        float wA = w1[s * S + f];
        float wB = w1[(S + s) * S + f];
        ull wAA = pack2(wA, wA), wBB = pack2(wB, wB);
        const ull* rowA = (const ull*)&bufA[s * BW + colbase];
        const ull* rowB = (const ull*)&bufB[s * BW + colbase];
        #pragma unroll
        for (int j = 0; j < NACC; j++) {
            aH[j] = ffma2(rowA[j], wAA, aH[j]);
            aH[j] = ffma2(rowB[j], wBB, aH[j]);
        }
    }
    __syncthreads();
    {
        float bb = b1[f];
        #pragma unroll
        for (int j = 0; j < NACC; j++) {
            float h0, h1v;
            unpack2(aH[j], h0, h1v);
            bufA[f * BW + colbase + 2 * j] = siluf(h0 + bb);
            bufA[f * BW + colbase + 2 * j + 1] = siluf(h1v + bb);
        }
    }
    __syncthreads();

    // a_sv, a_ss; final state -> REDG into graph accumulator
    ull aSV[NACC], aSS[NACC];
    #pragma unroll
    for (int j = 0; j < NACC; j++) { aSV[j] = 0ull; aSS[j] = 0ull; }
    #pragma unroll 2
    for (int s = 0; s < S; s++) {
        float wsv = w2[s * 3 * S + S + f];
        float wss = w2[s * 3 * S + 2 * S + f];
        ull wv2 = pack2(wsv, wsv), ws2 = pack2(wss, wss);
        const ull* row = (const ull*)&bufA[s * BW + colbase];
        #pragma unroll
        for (int j = 0; j < NACC; j++) {
            ull x = row[j];
            aSV[j] = ffma2(x, wv2, aSV[j]);
            aSS[j] = ffma2(x, ws2, aSS[j]);
        }
    }
    {
        float bsv = b2[S + f];
        float bss = b2[2 * S + f];
        #pragma unroll
        for (int j = 0; j < NACC; j++) {
            float sv0, sv1, ss0, ss1;
            unpack2(aSV[j], sv0, sv1);
            unpack2(aSS[j], ss0, ss1);
            int col = colbase + 2 * j;
            int nn0 = n0 + col;
            if (nn0 < N) {
                float v = (ss0 + bss) + 3.0f * sc[col] * (sv0 + bsv);
                atomicAdd(&g_graph[sgidx[col] * S + f], v);
            }
            if (nn0 + 1 < N) {
                float v = (ss1 + bss) + 3.0f * sc[col + 1] * (sv1 + bsv);
                atomicAdd(&g_graph[sgidx[col + 1] * S + f], v);
            }
        }
    }
}

// ---------------------------------------------------------------------------
// Output MLP per graph: 512 threads, split-K x4
// ---------------------------------------------------------------------------
__global__ void __launch_bounds__(512) k_out(
        const float* __restrict__ w1, const float* __restrict__ b1,
        const float* __restrict__ w2, const float* __restrict__ b2,
        float* __restrict__ out) {
    __shared__ float gs[S];
    __shared__ float part[4][S];
    __shared__ float red[4];
    int g = blockIdx.x, t = threadIdx.x;
    int f = t & 127;
    int q = t >> 7;      // 0..3
    if (t < S) gs[t] = g_graph[g * S + t];
    __syncthreads();
    // each quarter handles 32 s-values with 2 chains
    int sbase = q * 32;
    float a0 = 0.0f, a1 = 0.0f;
    #pragma unroll
    for (int i = 0; i < 32; i += 2) {
        a0 += gs[sbase + i] * w1[(sbase + i) * S + f];
        a1 += gs[sbase + i + 1] * w1[(sbase + i + 1) * S + f];
    }
    part[q][f] = a0 + a1;
    __syncthreads();
    if (t < S) {
        float hacc = b1[t] + (part[0][t] + part[1][t]) + (part[2][t] + part[3][t]);
        float h = hacc / (1.0f + expf(-hacc));
        float p = h * w2[t];
        #pragma unroll
        for (int m = 16; m; m >>= 1) p += __shfl_xor_sync(0xffffffffu, p, m);
        int w = t >> 5, lane = t & 31;
        if (lane == 0) red[w] = p;
    }
    __syncthreads();
    if (t == 0) out[g] = red[0] + red[1] + red[2] + red[3] + b2[0];
}

// ---------------------------------------------------------------------------
extern "C" void kernel_launch(void* const* d_in, const int* in_sizes, int n_in,
                              void* d_out, int out_size) {
    int N = in_sizes[3];
    int off = (n_in >= 22) ? 1 : 0;

    const float* diffs   = (const float*)d_in[0];
    const float* lens    = (const float*)d_in[1];
    const int*   gidx    = (const int*)d_in[3];
    const float* emb0    = (const float*)d_in[4 + off];
    const float* phi_w1  = (const float*)d_in[5 + off];
    const float* phi_b1  = (const float*)d_in[6 + off];
    const float* phi_w2  = (const float*)d_in[7 + off];
    const float* phi_b2  = (const float*)d_in[8 + off];
    const float* filt_w  = (const float*)d_in[9 + off];
    const float* filt_b  = (const float*)d_in[10 + off];
    const float* u_w     = (const float*)d_in[11 + off];
    const float* v_w     = (const float*)d_in[12 + off];
    const float* upd_w1  = (const float*)d_in[13 + off];
    const float* upd_b1  = (const float*)d_in[14 + off];
    const float* upd_w2  = (const float*)d_in[15 + off];
    const float* upd_b2  = (const float*)d_in[16 + off];
    const float* out_w1  = (const float*)d_in[17 + off];
    const float* out_b1  = (const float*)d_in[18 + off];
    const float* out_w2  = (const float*)d_in[19 + off];
    const float* out_b2  = (const float*)d_in[20 + off];
    float* out = (float*)d_out;
    int G = out_size;

    k_phi<<<1, 3 * S>>>(emb0, phi_w1, phi_b1, phi_w2, phi_b2);

    int nblk1 = (N + NPB - 1) / NPB;
    k_edge<<<nblk1, 256>>>(diffs, lens, filt_w, filt_b, N);

    int nblk2 = (N + BN - 1) / BN;
    k_node<<<nblk2, 256>>>(u_w, v_w, upd_w1, upd_b1, upd_w2, upd_b2, gidx, N);

    k_out<<<G, 512>>>(out_w1, out_b1, out_w2, out_b2, out);
}

// round 8
// speedup vs baseline: 1.7277x; 1.0723x over previous
#include <cuda_runtime.h>
#include <math.h>

#define S 128
#define NRBF 20
#define DEG 16
#define BN 36         // nodes per block (278 blocks = 1 wave @ 2/SM)
#define NCOL 18       // columns per 128-thread half
#define NACC 9        // f32x2 accumulators per half
#define BW 42         // padded tile width
#define GMAX 64

__device__ float g_phi[3 * S];
__device__ float g_graph[GMAX * S];

typedef unsigned long long ull;

// dynamic smem layout (floats)
#define OFF_BUFA 0
#define OFF_BUFB (S * BW)                     // 5376
#define OFF_SA   (2 * S * BW)                 // 10752
#define OFF_SB   (OFF_SA + BN * NRBF)         // +720
#define OFF_SAB  (OFF_SB + BN * 3 * NRBF)     // +2160
#define OFF_SBB  (OFF_SAB + BN)
#define OFF_SINV (OFF_SBB + 3 * BN)
#define OFF_SCP  (OFF_SINV + BN)
#define OFF_SC   (OFF_SCP + 8 * NCOL)
#define OFF_GIDX (OFF_SC + BN)
#define SMEM_FLOATS (OFF_GIDX + BN)
#define SMEM_BYTES (SMEM_FLOATS * 4)

__device__ __forceinline__ float siluf(float x) {
    return x / (1.0f + expf(-x));
}
__device__ __forceinline__ ull pack2(float a, float b) {
    ull r;
    asm("mov.b64 %0, {%1,%2};" : "=l"(r) : "f"(a), "f"(b));
    return r;
}
__device__ __forceinline__ ull ffma2(ull a, ull b, ull c) {
    ull d;
    asm("fma.rn.f32x2 %0, %1, %2, %3;" : "=l"(d) : "l"(a), "l"(b), "l"(c));
    return d;
}
__device__ __forceinline__ void unpack2(ull p, float& lo, float& hi) {
    asm("mov.b64 {%0,%1}, %2;" : "=f"(lo), "=f"(hi) : "l"(p));
}

// 4-lane 4-channel butterfly: lane (le&3) gets channel-le sum over 4 lanes
__device__ __forceinline__ float bf4x4(float q0, float q1, float q2, float q3, int le) {
    const unsigned FULL = 0xffffffffu;
    float a = (le & 1) ? q1 : q0;
    float b = (le & 1) ? q0 : q1;
    a += __shfl_xor_sync(FULL, b, 1);
    float c = (le & 1) ? q3 : q2;
    float d = (le & 1) ? q2 : q3;
    c += __shfl_xor_sync(FULL, d, 1);
    float e = (le & 2) ? c : a;
    float f = (le & 2) ? a : c;
    e += __shfl_xor_sync(FULL, f, 2);
    return e;
}

// ---------------------------------------------------------------------------
// Kernel 0: phi vector + zero graph accumulator (ILP'd)
// ---------------------------------------------------------------------------
__global__ void k_phi(const float* __restrict__ emb0,
                      const float* __restrict__ w1, const float* __restrict__ b1,
                      const float* __restrict__ w2, const float* __restrict__ b2) {
    __shared__ float h1[S];
    int t = threadIdx.x;
    for (int i = t; i < GMAX * S; i += 384) g_graph[i] = 0.0f;
    if (t < S) {
        float a0 = b1[t], a1 = 0.0f, a2 = 0.0f, a3 = 0.0f;
        #pragma unroll
        for (int s = 0; s < S; s += 4) {
            a0 += (128.0f * emb0[s + 0]) * w1[(s + 0) * S + t];
            a1 += (128.0f * emb0[s + 1]) * w1[(s + 1) * S + t];
            a2 += (128.0f * emb0[s + 2]) * w1[(s + 2) * S + t];
            a3 += (128.0f * emb0[s + 3]) * w1[(s + 3) * S + t];
        }
        h1[t] = siluf((a0 + a1) + (a2 + a3));
    }
    __syncthreads();
    if (t < 3 * S) {
        float a0 = b2[t], a1 = 0.0f, a2 = 0.0f, a3 = 0.0f;
        #pragma unroll
        for (int j = 0; j < S; j += 4) {
            a0 += h1[j + 0] * w2[(j + 0) * 3 * S + t];
            a1 += h1[j + 1] * w2[(j + 1) * 3 * S + t];
            a2 += h1[j + 2] * w2[(j + 2) * 3 * S + t];
            a3 += h1[j + 3] * w2[(j + 3) * 3 * S + t];
        }
        g_phi[t] = (a0 + a1) + (a2 + a3);
    }
}

// ---------------------------------------------------------------------------
// Fused kernel: edge stats + filter dots -> tiles -> per-node MLP -> atomics.
// BN=36 nodes, 256 threads.
// ---------------------------------------------------------------------------
__global__ void __launch_bounds__(256, 2) k_main(
        const float* __restrict__ diffs, const float* __restrict__ lens,
        const float* __restrict__ filt_w, const float* __restrict__ filt_b,
        const float* __restrict__ u_w, const float* __restrict__ v_w,
        const float* __restrict__ w1, const float* __restrict__ b1,
        const float* __restrict__ w2, const float* __restrict__ b2,
        const int* __restrict__ gidx, int N) {
    extern __shared__ __align__(16) float sm[];
    float* bufA = sm + OFF_BUFA;
    float* bufB = sm + OFF_BUFB;
    float* sA   = sm + OFF_SA;     // [BN][NRBF]
    float* sB   = sm + OFF_SB;     // [BN][3][NRBF]
    float* sAb  = sm + OFF_SAB;
    float* sBb  = sm + OFF_SBB;    // [BN][3]
    float* sInv = sm + OFF_SINV;
    float* scp  = sm + OFF_SCP;    // [8][NCOL]
    float* sc   = sm + OFF_SC;
    int* sgidx  = (int*)(sm + OFF_GIDX);

    const unsigned FULL = 0xffffffffu;
    int t = threadIdx.x;
    int f = t & 127;
    int h = t >> 7;
    int colbase = NCOL * h;
    int n0 = blockIdx.x * BN;

    if (t < BN) sgidx[t] = gidx[min(n0 + t, N - 1)];

    // ---- Edge stage: 4 lanes/node, 4 edges/lane (all threads participate) ----
    {
        int gi = t >> 2;
        int le = t & 3;
        bool valid = gi < BN;
        int nc = min(n0 + min(gi, BN - 1), N - 1);
        int e0 = nc * DEG + le * 4;
        const float4* dp = (const float4*)(diffs + 3 * e0);
        float4 d0 = dp[0], d1 = dp[1], d2 = dp[2];
        float4 lv = *(const float4*)(lens + e0);
        float dx[4] = {d0.x, d0.w, d1.z, d2.y};
        float dy[4] = {d0.y, d1.x, d1.w, d2.z};
        float dz[4] = {d0.z, d1.y, d2.x, d2.w};
        float ln[4] = {lv.x, lv.y, lv.z, lv.w};
        float pir[4], pre[4], sk[4], skm[4], cc[4];
        float fr = 0.0f;
        #pragma unroll
        for (int j = 0; j < 4; j++) {
            float r2 = dx[j] * dx[j] + dy[j] * dy[j] + dz[j] * dz[j];
            float r = sqrtf(r2);
            float m = (fabsf(ln[j]) <= 10.0f) ? 1.0f : 0.0f;
            float rs = fmaxf(r, 1e-12f);
            float b = rs * 0.1f;
            float c = cospif(b);
            float s = sinpif(b);
            float cut = (r < 10.0f) ? 0.5f * (c + 1.0f) : 0.0f;
            pre[j] = m * cut;
            pir[j] = m * cut / rs;
            sk[j] = s; skm[j] = 0.0f; cc[j] = 2.0f * c;
            fr += m * r2;
        }
        fr += __shfl_xor_sync(FULL, fr, 1);
        fr += __shfl_xor_sync(FULL, fr, 2);
        if (valid && le == 0) {
            float frob = sqrtf(fr);
            sInv[gi] = 1.0f / ((frob > 0.0f) ? frob : 1.0f);
        }
        {
            float q0 = pre[0] + pre[1] + pre[2] + pre[3];
            float q1 = pre[0] * dx[0] + pre[1] * dx[1] + pre[2] * dx[2] + pre[3] * dx[3];
            float q2 = pre[0] * dy[0] + pre[1] * dy[1] + pre[2] * dy[2] + pre[3] * dy[3];
            float q3 = pre[0] * dz[0] + pre[1] * dz[1] + pre[2] * dz[2] + pre[3] * dz[3];
            float v = bf4x4(q0, q1, q2, q3, le);
            if (valid) {
                if (le == 0) sAb[gi] = v;
                else sBb[gi * 3 + le - 1] = v;
            }
        }
        #pragma unroll
        for (int k = 0; k < NRBF; k++) {
            float a0 = pir[0] * sk[0];
            float a1 = pir[1] * sk[1];
            float a2 = pir[2] * sk[2];
            float a3 = pir[3] * sk[3];
            float q0 = (a0 + a1) + (a2 + a3);
            float q1 = a0 * dx[0] + a1 * dx[1] + a2 * dx[2] + a3 * dx[3];
            float q2 = a0 * dy[0] + a1 * dy[1] + a2 * dy[2] + a3 * dy[3];
            float q3 = a0 * dz[0] + a1 * dz[1] + a2 * dz[2] + a3 * dz[3];
            float v = bf4x4(q0, q1, q2, q3, le);
            if (valid) {
                if (le == 0) sA[gi * NRBF + k] = v;
                else sB[(gi * 3 + le - 1) * NRBF + k] = v;
            }
            #pragma unroll
            for (int j = 0; j < 4; j++) {
                float sn = cc[j] * sk[j] - skm[j];
                skm[j] = sk[j];
                sk[j] = sn;
            }
        }
    }
    __syncthreads();

    // ---- Filter dots -> tiles (each half handles its 18 columns) ----
    {
        int c = f % 3;
        float phi2 = g_phi[S + f];
        float phi3 = g_phi[2 * S + f];
        float fb2 = filt_b[S + f];
        float fb3 = filt_b[2 * S + f];

        ull w2p[NRBF / 2], w3p[NRBF / 2];
        #pragma unroll
        for (int kk = 0; kk < NRBF / 2; kk++) {
            w2p[kk] = pack2(filt_w[(2 * kk) * 3 * S + S + f],
                            filt_w[(2 * kk + 1) * 3 * S + S + f]);
            w3p[kk] = pack2(filt_w[(2 * kk) * 3 * S + 2 * S + f],
                            filt_w[(2 * kk + 1) * 3 * S + 2 * S + f]);
        }
        #pragma unroll
        for (int ni = 0; ni < NCOL; ni++) {
            int col = colbase + ni;
            ull acc2 = 0ull, acc3 = 0ull;
            const ull* pa = (const ull*)&sA[col * NRBF];
            const ull* pb = (const ull*)&sB[(col * 3 + c) * NRBF];
            #pragma unroll
            for (int kk = 0; kk < NRBF / 2; kk++) {
                acc2 = ffma2(pa[kk], w2p[kk], acc2);
                acc3 = ffma2(pb[kk], w3p[kk], acc3);
            }
            float a2l, a2h, a3l, a3h;
            unpack2(acc2, a2l, a2h);
            unpack2(acc3, a3l, a3h);
            bufB[f * BW + col] = phi2 * (a2l + a2h + sAb[col] * fb2);
            bufA[f * BW + col] = phi3 * (a3l + a3h + sBb[col * 3 + c] * fb3) * sInv[col];
        }
    }
    __syncthreads();

    // ---- U, V matmuls ----
    ull aU[NACC], aV[NACC];
    #pragma unroll
    for (int j = 0; j < NACC; j++) { aU[j] = 0ull; aV[j] = 0ull; }
    #pragma unroll 2
    for (int s = 0; s < S; s++) {
        float wu = u_w[s * S + f];
        float wv = v_w[s * S + f];
        ull wuu = pack2(wu, wu), wvv = pack2(wv, wv);
        const ull* row = (const ull*)&bufA[s * BW + colbase];
        #pragma unroll
        for (int j = 0; j < NACC; j++) {
            ull x = row[j];
            aU[j] = ffma2(x, wuu, aU[j]);
            aV[j] = ffma2(x, wvv, aV[j]);
        }
    }
    __syncthreads();

    const float SQ3 = 1.7320508075688772f;
    float prod[NCOL];
    #pragma unroll
    for (int j = 0; j < NACC; j++) {
        float u0, u1, v0, v1;
        unpack2(aU[j], u0, u1);
        unpack2(aV[j], v0, v1);
        prod[2 * j] = u0 * v0;
        prod[2 * j + 1] = u1 * v1;
        bufA[f * BW + colbase + 2 * j] = SQ3 * fabsf(v0);
        bufA[f * BW + colbase + 2 * j + 1] = SQ3 * fabsf(v1);
    }
    int w = t >> 5, lane = t & 31;
    #pragma unroll
    for (int ni = 0; ni < NCOL; ni++) {
        float v = prod[ni];
        #pragma unroll
        for (int m = 16; m; m >>= 1) v += __shfl_xor_sync(FULL, v, m);
        if (lane == 0) scp[w * NCOL + ni] = v;
    }
    __syncthreads();
    if (t < BN) {
        int hh = t / NCOL, ni = t % NCOL;
        int wb = hh * 4;
        sc[t] = scp[wb * NCOL + ni] + scp[(wb + 1) * NCOL + ni] +
                scp[(wb + 2) * NCOL + ni] + scp[(wb + 3) * NCOL + ni];
    }
    __syncthreads();

    // ---- h = silu([Vnorm, state1] @ upd_w1 + b1) ----
    ull aH[NACC];
    #pragma unroll
    for (int j = 0; j < NACC; j++) aH[j] = 0ull;
    #pragma unroll 2
    for (int s = 0; s < S; s++) {
        float wA = w1[s * S + f];
        float wB = w1[(S + s) * S + f];
        ull wAA = pack2(wA, wA), wBB = pack2(wB, wB);
        const ull* rowA = (const ull*)&bufA[s * BW + colbase];
        const ull* rowB = (const ull*)&bufB[s * BW + colbase];
        #pragma unroll
        for (int j = 0; j < NACC; j++) {
            aH[j] = ffma2(rowA[j], wAA, aH[j]);
            aH[j] = ffma2(rowB[j], wBB, aH[j]);
        }
    }
    __syncthreads();
    {
        float bb = b1[f];
        #pragma unroll
        for (int j = 0; j < NACC; j++) {
            float h0, h1v;
            unpack2(aH[j], h0, h1v);
            bufA[f * BW + colbase + 2 * j] = siluf(h0 + bb);
            bufA[f * BW + colbase + 2 * j + 1] = siluf(h1v + bb);
        }
    }
    __syncthreads();

    // ---- a_sv, a_ss; final state -> REDG into graph accumulator ----
    ull aSV[NACC], aSS[NACC];
    #pragma unroll
    for (int j = 0; j < NACC; j++) { aSV[j] = 0ull; aSS[j] = 0ull; }
    #pragma unroll 2
    for (int s = 0; s < S; s++) {
        float wsv = w2[s * 3 * S + S + f];
        float wss = w2[s * 3 * S + 2 * S + f];
        ull wv2 = pack2(wsv, wsv), ws2 = pack2(wss, wss);
        const ull* row = (const ull*)&bufA[s * BW + colbase];
        #pragma unroll
        for (int j = 0; j < NACC; j++) {
            ull x = row[j];
            aSV[j] = ffma2(x, wv2, aSV[j]);
            aSS[j] = ffma2(x, ws2, aSS[j]);
        }
    }
    {
        float bsv = b2[S + f];
        float bss = b2[2 * S + f];
        #pragma unroll
        for (int j = 0; j < NACC; j++) {
            float sv0, sv1, ss0, ss1;
            unpack2(aSV[j], sv0, sv1);
            unpack2(aSS[j], ss0, ss1);
            int col = colbase + 2 * j;
            int nn0 = n0 + col;
            if (nn0 < N) {
                float v = (ss0 + bss) + 3.0f * sc[col] * (sv0 + bsv);
                atomicAdd(&g_graph[sgidx[col] * S + f], v);
            }
            if (nn0 + 1 < N) {
                float v = (ss1 + bss) + 3.0f * sc[col + 1] * (sv1 + bsv);
                atomicAdd(&g_graph[sgidx[col + 1] * S + f], v);
            }
        }
    }
}

// ---------------------------------------------------------------------------
// Output MLP per graph: 512 threads, split-K x4
// ---------------------------------------------------------------------------
__global__ void __launch_bounds__(512) k_out(
        const float* __restrict__ w1, const float* __restrict__ b1,
        const float* __restrict__ w2, const float* __restrict__ b2,
        float* __restrict__ out) {
    __shared__ float gs[S];
    __shared__ float part[4][S];
    __shared__ float red[4];
    int g = blockIdx.x, t = threadIdx.x;
    int f = t & 127;
    int q = t >> 7;
    if (t < S) gs[t] = g_graph[g * S + t];
    __syncthreads();
    int sbase = q * 32;
    float a0 = 0.0f, a1 = 0.0f;
    #pragma unroll
    for (int i = 0; i < 32; i += 2) {
        a0 += gs[sbase + i] * w1[(sbase + i) * S + f];
        a1 += gs[sbase + i + 1] * w1[(sbase + i + 1) * S + f];
    }
    part[q][f] = a0 + a1;
    __syncthreads();
    if (t < S) {
        float hacc = b1[t] + (part[0][t] + part[1][t]) + (part[2][t] + part[3][t]);
        float h = hacc / (1.0f + expf(-hacc));
        float p = h * w2[t];
        #pragma unroll
        for (int m = 16; m; m >>= 1) p += __shfl_xor_sync(0xffffffffu, p, m);
        int w = t >> 5, lane = t & 31;
        if (lane == 0) red[w] = p;
    }
    __syncthreads();
    if (t == 0) out[g] = red[0] + red[1] + red[2] + red[3] + b2[0];
}

// ---------------------------------------------------------------------------
extern "C" void kernel_launch(void* const* d_in, const int* in_sizes, int n_in,
                              void* d_out, int out_size) {
    int N = in_sizes[3];
    int off = (n_in >= 22) ? 1 : 0;

    const float* diffs   = (const float*)d_in[0];
    const float* lens    = (const float*)d_in[1];
    const int*   gidx    = (const int*)d_in[3];
    const float* emb0    = (const float*)d_in[4 + off];
    const float* phi_w1  = (const float*)d_in[5 + off];
    const float* phi_b1  = (const float*)d_in[6 + off];
    const float* phi_w2  = (const float*)d_in[7 + off];
    const float* phi_b2  = (const float*)d_in[8 + off];
    const float* filt_w  = (const float*)d_in[9 + off];
    const float* filt_b  = (const float*)d_in[10 + off];
    const float* u_w     = (const float*)d_in[11 + off];
    const float* v_w     = (const float*)d_in[12 + off];
    const float* upd_w1  = (const float*)d_in[13 + off];
    const float* upd_b1  = (const float*)d_in[14 + off];
    const float* upd_w2  = (const float*)d_in[15 + off];
    const float* upd_b2  = (const float*)d_in[16 + off];
    const float* out_w1  = (const float*)d_in[17 + off];
    const float* out_b1  = (const float*)d_in[18 + off];
    const float* out_w2  = (const float*)d_in[19 + off];
    const float* out_b2  = (const float*)d_in[20 + off];
    float* out = (float*)d_out;
    int G = out_size;

    cudaFuncSetAttribute(k_main, cudaFuncAttributeMaxDynamicSharedMemorySize,
                         SMEM_BYTES);

    k_phi<<<1, 3 * S>>>(emb0, phi_w1, phi_b1, phi_w2, phi_b2);

    int nblk = (N + BN - 1) / BN;
    k_main<<<nblk, 256, SMEM_BYTES>>>(diffs, lens, filt_w, filt_b,
                                      u_w, v_w, upd_w1, upd_b1, upd_w2, upd_b2,
                                      gidx, N);

    k_out<<<G, 512>>>(out_w1, out_b1, out_w2, out_b2, out);
}

// round 9
// speedup vs baseline: 1.7422x; 1.0084x over previous
#include <cuda_runtime.h>
#include <math.h>

#define S 128
#define NRBF 20
#define DEG 16
#define BN 36         // nodes per block (278 blocks = 1 wave @ 2/SM)
#define NCOL 18       // columns per 128-thread half
#define NACC 9        // f32x2 accumulators per half
#define BW 42         // padded tile width
#define GMAX 64
#define PHI_BLOCKS 8

__device__ float g_phi[3 * S];
__device__ float g_graph[GMAX * S];

typedef unsigned long long ull;

// dynamic smem layout (floats)
#define OFF_BUFA 0
#define OFF_BUFB (S * BW)
#define OFF_SA   (2 * S * BW)
#define OFF_SB   (OFF_SA + BN * NRBF)
#define OFF_SAB  (OFF_SB + BN * 3 * NRBF)
#define OFF_SBB  (OFF_SAB + BN)
#define OFF_SINV (OFF_SBB + 3 * BN)
#define OFF_SCP  (OFF_SINV + BN)
#define OFF_SC   (OFF_SCP + 8 * NCOL)
#define OFF_GIDX (OFF_SC + BN)
#define SMEM_FLOATS (OFF_GIDX + BN)
#define SMEM_BYTES (SMEM_FLOATS * 4)

__device__ __forceinline__ float siluf(float x) {
    return x / (1.0f + expf(-x));
}
__device__ __forceinline__ ull pack2(float a, float b) {
    ull r;
    asm("mov.b64 %0, {%1,%2};" : "=l"(r) : "f"(a), "f"(b));
    return r;
}
__device__ __forceinline__ ull ffma2(ull a, ull b, ull c) {
    ull d;
    asm("fma.rn.f32x2 %0, %1, %2, %3;" : "=l"(d) : "l"(a), "l"(b), "l"(c));
    return d;
}
__device__ __forceinline__ void unpack2(ull p, float& lo, float& hi) {
    asm("mov.b64 {%0,%1}, %2;" : "=f"(lo), "=f"(hi) : "l"(p));
}

// 4-lane 4-channel butterfly
__device__ __forceinline__ float bf4x4(float q0, float q1, float q2, float q3, int le) {
    const unsigned FULL = 0xffffffffu;
    float a = (le & 1) ? q1 : q0;
    float b = (le & 1) ? q0 : q1;
    a += __shfl_xor_sync(FULL, b, 1);
    float c = (le & 1) ? q3 : q2;
    float d = (le & 1) ? q2 : q3;
    c += __shfl_xor_sync(FULL, d, 1);
    float e = (le & 2) ? c : a;
    float f = (le & 2) ? a : c;
    e += __shfl_xor_sync(FULL, f, 2);
    return e;
}

// ---------------------------------------------------------------------------
// Kernel 0: phi vector, parallelized over PHI_BLOCKS blocks.
// Stage 1 (h1) redundant per block (split-K x3); stage 2 split 48 outputs/block.
// Also zeros the graph accumulator.
// ---------------------------------------------------------------------------
__global__ void __launch_bounds__(384) k_phi(
        const float* __restrict__ emb0,
        const float* __restrict__ w1, const float* __restrict__ b1,
        const float* __restrict__ w2, const float* __restrict__ b2) {
    __shared__ float se[S];
    __shared__ float part1[3][S];
    __shared__ float h1[S];
    __shared__ float part2[8][48];
    int t = threadIdx.x;
    int b = blockIdx.x;

    for (int i = b * 384 + t; i < GMAX * S; i += PHI_BLOCKS * 384)
        g_graph[i] = 0.0f;

    if (t < S) se[t] = 128.0f * emb0[t];
    __syncthreads();

    // stage 1: f = t&127, q = t>>7 in {0,1,2}; k-chunks 43/43/42
    {
        int f = t & 127;
        int q = t >> 7;
        int k0 = q * 43;
        int k1 = min(k0 + 43, S);
        float a0 = 0.0f, a1 = 0.0f;
        for (int k = k0; k + 1 < k1; k += 2) {
            a0 += se[k] * w1[k * S + f];
            a1 += se[k + 1] * w1[(k + 1) * S + f];
        }
        if ((k1 - k0) & 1) a0 += se[k1 - 1] * w1[(k1 - 1) * S + f];
        part1[q][f] = a0 + a1;
    }
    __syncthreads();
    if (t < S)
        h1[t] = siluf(b1[t] + part1[0][t] + part1[1][t] + part1[2][t]);
    __syncthreads();

    // stage 2: block b owns outputs [b*48, b*48+48); 8 k-chunks of 16
    {
        int ol = t % 48;
        int q8 = t / 48;
        int o = b * 48 + ol;
        int kk0 = q8 * 16;
        float a0 = 0.0f, a1 = 0.0f;
        #pragma unroll
        for (int i = 0; i < 16; i += 2) {
            a0 += h1[kk0 + i] * w2[(kk0 + i) * 3 * S + o];
            a1 += h1[kk0 + i + 1] * w2[(kk0 + i + 1) * 3 * S + o];
        }
        part2[q8][ol] = a0 + a1;
    }
    __syncthreads();
    if (t < 48) {
        int o = b * 48 + t;
        float s = b2[o];
        #pragma unroll
        for (int j = 0; j < 8; j++) s += part2[j][t];
        g_phi[o] = s;
    }
}

// ---------------------------------------------------------------------------
// Fused kernel: edge stats + filter dots -> tiles -> per-node MLP -> atomics.
// ---------------------------------------------------------------------------
__global__ void __launch_bounds__(256, 2) k_main(
        const float* __restrict__ diffs, const float* __restrict__ lens,
        const float* __restrict__ filt_w, const float* __restrict__ filt_b,
        const float* __restrict__ u_w, const float* __restrict__ v_w,
        const float* __restrict__ w1, const float* __restrict__ b1,
        const float* __restrict__ w2, const float* __restrict__ b2,
        const int* __restrict__ gidx, int N) {
    extern __shared__ __align__(16) float sm[];
    float* bufA = sm + OFF_BUFA;
    float* bufB = sm + OFF_BUFB;
    float* sA   = sm + OFF_SA;
    float* sB   = sm + OFF_SB;
    float* sAb  = sm + OFF_SAB;
    float* sBb  = sm + OFF_SBB;
    float* sInv = sm + OFF_SINV;
    float* scp  = sm + OFF_SCP;
    float* sc   = sm + OFF_SC;
    int* sgidx  = (int*)(sm + OFF_GIDX);

    const unsigned FULL = 0xffffffffu;
    int t = threadIdx.x;
    int f = t & 127;
    int h = t >> 7;
    int colbase = NCOL * h;
    int n0 = blockIdx.x * BN;

    if (t < BN) sgidx[t] = gidx[min(n0 + t, N - 1)];

    // ---- Edge stage: 4 lanes/node, 4 edges/lane ----
    {
        int gi = t >> 2;
        int le = t & 3;
        bool valid = gi < BN;
        int nc = min(n0 + min(gi, BN - 1), N - 1);
        int e0 = nc * DEG + le * 4;
        const float4* dp = (const float4*)(diffs + 3 * e0);
        float4 d0 = dp[0], d1 = dp[1], d2 = dp[2];
        float4 lv = *(const float4*)(lens + e0);
        float dx[4] = {d0.x, d0.w, d1.z, d2.y};
        float dy[4] = {d0.y, d1.x, d1.w, d2.z};
        float dz[4] = {d0.z, d1.y, d2.x, d2.w};
        float ln[4] = {lv.x, lv.y, lv.z, lv.w};
        float pir[4], pre[4], sk[4], skm[4], cc[4];
        float fr = 0.0f;
        #pragma unroll
        for (int j = 0; j < 4; j++) {
            float r2 = dx[j] * dx[j] + dy[j] * dy[j] + dz[j] * dz[j];
            float r = sqrtf(r2);
            float m = (fabsf(ln[j]) <= 10.0f) ? 1.0f : 0.0f;
            float rs = fmaxf(r, 1e-12f);
            float bq = rs * 0.1f;
            float c = cospif(bq);
            float s = sinpif(bq);
            float cut = (r < 10.0f) ? 0.5f * (c + 1.0f) : 0.0f;
            pre[j] = m * cut;
            pir[j] = m * cut / rs;
            sk[j] = s; skm[j] = 0.0f; cc[j] = 2.0f * c;
            fr += m * r2;
        }
        fr += __shfl_xor_sync(FULL, fr, 1);
        fr += __shfl_xor_sync(FULL, fr, 2);
        if (valid && le == 0) {
            float frob = sqrtf(fr);
            sInv[gi] = 1.0f / ((frob > 0.0f) ? frob : 1.0f);
        }
        {
            float q0 = pre[0] + pre[1] + pre[2] + pre[3];
            float q1 = pre[0] * dx[0] + pre[1] * dx[1] + pre[2] * dx[2] + pre[3] * dx[3];
            float q2 = pre[0] * dy[0] + pre[1] * dy[1] + pre[2] * dy[2] + pre[3] * dy[3];
            float q3 = pre[0] * dz[0] + pre[1] * dz[1] + pre[2] * dz[2] + pre[3] * dz[3];
            float v = bf4x4(q0, q1, q2, q3, le);
            if (valid) {
                if (le == 0) sAb[gi] = v;
                else sBb[gi * 3 + le - 1] = v;
            }
        }
        #pragma unroll
        for (int k = 0; k < NRBF; k++) {
            float a0 = pir[0] * sk[0];
            float a1 = pir[1] * sk[1];
            float a2 = pir[2] * sk[2];
            float a3 = pir[3] * sk[3];
            float q0 = (a0 + a1) + (a2 + a3);
            float q1 = a0 * dx[0] + a1 * dx[1] + a2 * dx[2] + a3 * dx[3];
            float q2 = a0 * dy[0] + a1 * dy[1] + a2 * dy[2] + a3 * dy[3];
            float q3 = a0 * dz[0] + a1 * dz[1] + a2 * dz[2] + a3 * dz[3];
            float v = bf4x4(q0, q1, q2, q3, le);
            if (valid) {
                if (le == 0) sA[gi * NRBF + k] = v;
                else sB[(gi * 3 + le - 1) * NRBF + k] = v;
            }
            #pragma unroll
            for (int j = 0; j < 4; j++) {
                float sn = cc[j] * sk[j] - skm[j];
                skm[j] = sk[j];
                sk[j] = sn;
            }
        }
    }
    __syncthreads();

    // ---- Filter dots -> tiles ----
    {
        int c = f % 3;
        float phi2 = g_phi[S + f];
        float phi3 = g_phi[2 * S + f];
        float fb2 = filt_b[S + f];
        float fb3 = filt_b[2 * S + f];

        ull w2p[NRBF / 2], w3p[NRBF / 2];
        #pragma unroll
        for (int kk = 0; kk < NRBF / 2; kk++) {
            w2p[kk] = pack2(filt_w[(2 * kk) * 3 * S + S + f],
                            filt_w[(2 * kk + 1) * 3 * S + S + f]);
            w3p[kk] = pack2(filt_w[(2 * kk) * 3 * S + 2 * S + f],
                            filt_w[(2 * kk + 1) * 3 * S + 2 * S + f]);
        }
        #pragma unroll
        for (int ni = 0; ni < NCOL; ni++) {
            int col = colbase + ni;
            ull acc2 = 0ull, acc3 = 0ull;
            const ull* pa = (const ull*)&sA[col * NRBF];
            const ull* pb = (const ull*)&sB[(col * 3 + c) * NRBF];
            #pragma unroll
            for (int kk = 0; kk < NRBF / 2; kk++) {
                acc2 = ffma2(pa[kk], w2p[kk], acc2);
                acc3 = ffma2(pb[kk], w3p[kk], acc3);
            }
            float a2l, a2h, a3l, a3h;
            unpack2(acc2, a2l, a2h);
            unpack2(acc3, a3l, a3h);
            bufB[f * BW + col] = phi2 * (a2l + a2h + sAb[col] * fb2);
            bufA[f * BW + col] = phi3 * (a3l + a3h + sBb[col * 3 + c] * fb3) * sInv[col];
        }
    }
    __syncthreads();

    // ---- U, V matmuls ----
    ull aU[NACC], aV[NACC];
    #pragma unroll
    for (int j = 0; j < NACC; j++) { aU[j] = 0ull; aV[j] = 0ull; }
    #pragma unroll 2
    for (int s = 0; s < S; s++) {
        float wu = u_w[s * S + f];
        float wv = v_w[s * S + f];
        ull wuu = pack2(wu, wu), wvv = pack2(wv, wv);
        const ull* row = (const ull*)&bufA[s * BW + colbase];
        #pragma unroll
        for (int j = 0; j < NACC; j++) {
            ull x = row[j];
            aU[j] = ffma2(x, wuu, aU[j]);
            aV[j] = ffma2(x, wvv, aV[j]);
        }
    }
    __syncthreads();

    const float SQ3 = 1.7320508075688772f;
    float prod[NCOL];
    #pragma unroll
    for (int j = 0; j < NACC; j++) {
        float u0, u1, v0, v1;
        unpack2(aU[j], u0, u1);
        unpack2(aV[j], v0, v1);
        prod[2 * j] = u0 * v0;
        prod[2 * j + 1] = u1 * v1;
        bufA[f * BW + colbase + 2 * j] = SQ3 * fabsf(v0);
        bufA[f * BW + colbase + 2 * j + 1] = SQ3 * fabsf(v1);
    }
    int w = t >> 5, lane = t & 31;
    #pragma unroll
    for (int ni = 0; ni < NCOL; ni++) {
        float v = prod[ni];
        #pragma unroll
        for (int m = 16; m; m >>= 1) v += __shfl_xor_sync(FULL, v, m);
        if (lane == 0) scp[w * NCOL + ni] = v;
    }
    __syncthreads();
    if (t < BN) {
        int hh = t / NCOL, ni = t % NCOL;
        int wb = hh * 4;
        sc[t] = scp[wb * NCOL + ni] + scp[(wb + 1) * NCOL + ni] +
                scp[(wb + 2) * NCOL + ni] + scp[(wb + 3) * NCOL + ni];
    }
    __syncthreads();

    // ---- h = silu([Vnorm, state1] @ upd_w1 + b1) ----
    ull aH[NACC];
    #pragma unroll
    for (int j = 0; j < NACC; j++) aH[j] = 0ull;
    #pragma unroll 2
    for (int s = 0; s < S; s++) {
        float wA = w1[s * S + f];
        float wB = w1[(S + s) * S + f];
        ull wAA = pack2(wA, wA), wBB = pack2(wB, wB);
        const ull* rowA = (const ull*)&bufA[s * BW + colbase];
        const ull* rowB = (const ull*)&bufB[s * BW + colbase];
        #pragma unroll
        for (int j = 0; j < NACC; j++) {
            aH[j] = ffma2(rowA[j], wAA, aH[j]);
            aH[j] = ffma2(rowB[j], wBB, aH[j]);
        }
    }
    __syncthreads();
    {
        float bb = b1[f];
        #pragma unroll
        for (int j = 0; j < NACC; j++) {
            float h0, h1v;
            unpack2(aH[j], h0, h1v);
            bufA[f * BW + colbase + 2 * j] = siluf(h0 + bb);
            bufA[f * BW + colbase + 2 * j + 1] = siluf(h1v + bb);
        }
    }
    __syncthreads();

    // ---- a_sv, a_ss; final state -> REDG into graph accumulator ----
    ull aSV[NACC], aSS[NACC];
    #pragma unroll
    for (int j = 0; j < NACC; j++) { aSV[j] = 0ull; aSS[j] = 0ull; }
    #pragma unroll 2
    for (int s = 0; s < S; s++) {
        float wsv = w2[s * 3 * S + S + f];
        float wss = w2[s * 3 * S + 2 * S + f];
        ull wv2 = pack2(wsv, wsv), ws2 = pack2(wss, wss);
        const ull* row = (const ull*)&bufA[s * BW + colbase];
        #pragma unroll
        for (int j = 0; j < NACC; j++) {
            ull x = row[j];
            aSV[j] = ffma2(x, wv2, aSV[j]);
            aSS[j] = ffma2(x, ws2, aSS[j]);
        }
    }
    {
        float bsv = b2[S + f];
        float bss = b2[2 * S + f];
        #pragma unroll
        for (int j = 0; j < NACC; j++) {
            float sv0, sv1, ss0, ss1;
            unpack2(aSV[j], sv0, sv1);
            unpack2(aSS[j], ss0, ss1);
            int col = colbase + 2 * j;
            int nn0 = n0 + col;
            if (nn0 < N) {
                float v = (ss0 + bss) + 3.0f * sc[col] * (sv0 + bsv);
                atomicAdd(&g_graph[sgidx[col] * S + f], v);
            }
            if (nn0 + 1 < N) {
                float v = (ss1 + bss) + 3.0f * sc[col + 1] * (sv1 + bsv);
                atomicAdd(&g_graph[sgidx[col + 1] * S + f], v);
            }
        }
    }
}

// ---------------------------------------------------------------------------
// Output MLP per graph: 512 threads, split-K x4
// ---------------------------------------------------------------------------
__global__ void __launch_bounds__(512) k_out(
        const float* __restrict__ w1, const float* __restrict__ b1,
        const float* __restrict__ w2, const float* __restrict__ b2,
        float* __restrict__ out) {
    __shared__ float gs[S];
    __shared__ float part[4][S];
    __shared__ float red[4];
    int g = blockIdx.x, t = threadIdx.x;
    int f = t & 127;
    int q = t >> 7;
    if (t < S) gs[t] = g_graph[g * S + t];
    __syncthreads();
    int sbase = q * 32;
    float a0 = 0.0f, a1 = 0.0f;
    #pragma unroll
    for (int i = 0; i < 32; i += 2) {
        a0 += gs[sbase + i] * w1[(sbase + i) * S + f];
        a1 += gs[sbase + i + 1] * w1[(sbase + i + 1) * S + f];
    }
    part[q][f] = a0 + a1;
    __syncthreads();
    if (t < S) {
        float hacc = b1[t] + (part[0][t] + part[1][t]) + (part[2][t] + part[3][t]);
        float h = hacc / (1.0f + expf(-hacc));
        float p = h * w2[t];
        #pragma unroll
        for (int m = 16; m; m >>= 1) p += __shfl_xor_sync(0xffffffffu, p, m);
        int w = t >> 5, lane = t & 31;
        if (lane == 0) red[w] = p;
    }
    __syncthreads();
    if (t == 0) out[g] = red[0] + red[1] + red[2] + red[3] + b2[0];
}

// ---------------------------------------------------------------------------
extern "C" void kernel_launch(void* const* d_in, const int* in_sizes, int n_in,
                              void* d_out, int out_size) {
    int N = in_sizes[3];
    int off = (n_in >= 22) ? 1 : 0;

    const float* diffs   = (const float*)d_in[0];
    const float* lens    = (const float*)d_in[1];
    const int*   gidx    = (const int*)d_in[3];
    const float* emb0    = (const float*)d_in[4 + off];
    const float* phi_w1  = (const float*)d_in[5 + off];
    const float* phi_b1  = (const float*)d_in[6 + off];
    const float* phi_w2  = (const float*)d_in[7 + off];
    const float* phi_b2  = (const float*)d_in[8 + off];
    const float* filt_w  = (const float*)d_in[9 + off];
    const float* filt_b  = (const float*)d_in[10 + off];
    const float* u_w     = (const float*)d_in[11 + off];
    const float* v_w     = (const float*)d_in[12 + off];
    const float* upd_w1  = (const float*)d_in[13 + off];
    const float* upd_b1  = (const float*)d_in[14 + off];
    const float* upd_w2  = (const float*)d_in[15 + off];
    const float* upd_b2  = (const float*)d_in[16 + off];
    const float* out_w1  = (const float*)d_in[17 + off];
    const float* out_b1  = (const float*)d_in[18 + off];
    const float* out_w2  = (const float*)d_in[19 + off];
    const float* out_b2  = (const float*)d_in[20 + off];
    float* out = (float*)d_out;
    int G = out_size;

    cudaFuncSetAttribute(k_main, cudaFuncAttributeMaxDynamicSharedMemorySize,
                         SMEM_BYTES);

    k_phi<<<PHI_BLOCKS, 384>>>(emb0, phi_w1, phi_b1, phi_w2, phi_b2);

    int nblk = (N + BN - 1) / BN;
    k_main<<<nblk, 256, SMEM_BYTES>>>(diffs, lens, filt_w, filt_b,
                                      u_w, v_w, upd_w1, upd_b1, upd_w2, upd_b2,
                                      gidx, N);

    k_out<<<G, 512>>>(out_w1, out_b1, out_w2, out_b2, out);
}

// round 10
// speedup vs baseline: 1.7816x; 1.0227x over previous
#include <cuda_runtime.h>
#include <math.h>

#define S 128
#define NRBF 20
#define DEG 16
#define BN 36         // nodes per block (278 blocks = 1 wave @ 2/SM)
#define NCOL 18       // columns per 128-thread half
#define NACC 9        // f32x2 accumulators per half
#define BW 42         // padded tile width
#define GMAX 64
#define PHI_BLOCKS 8

__device__ float g_phi[3 * S];
__device__ float g_graph[GMAX * S];

typedef unsigned long long ull;

// dynamic smem layout (floats)
#define OFF_BUFA 0
#define OFF_BUFB (S * BW)
#define OFF_SA   (2 * S * BW)
#define OFF_SB   (OFF_SA + BN * NRBF)
#define OFF_SAB  (OFF_SB + BN * 3 * NRBF)
#define OFF_SBB  (OFF_SAB + BN)
#define OFF_SINV (OFF_SBB + 3 * BN)
#define OFF_SCP  (OFF_SINV + BN)
#define OFF_SC   (OFF_SCP + 8 * NCOL)
#define OFF_GIDX (OFF_SC + BN)
#define SMEM_FLOATS (OFF_GIDX + BN)
#define SMEM_BYTES (SMEM_FLOATS * 4)

__device__ __forceinline__ float siluf(float x) {
    return x / (1.0f + expf(-x));
}
__device__ __forceinline__ ull pack2(float a, float b) {
    ull r;
    asm("mov.b64 %0, {%1,%2};" : "=l"(r) : "f"(a), "f"(b));
    return r;
}
__device__ __forceinline__ ull ffma2(ull a, ull b, ull c) {
    ull d;
    asm("fma.rn.f32x2 %0, %1, %2, %3;" : "=l"(d) : "l"(a), "l"(b), "l"(c));
    return d;
}
__device__ __forceinline__ void unpack2(ull p, float& lo, float& hi) {
    asm("mov.b64 {%0,%1}, %2;" : "=f"(lo), "=f"(hi) : "l"(p));
}

// 4-lane 4-channel butterfly
__device__ __forceinline__ float bf4x4(float q0, float q1, float q2, float q3, int le) {
    const unsigned FULL = 0xffffffffu;
    float a = (le & 1) ? q1 : q0;
    float b = (le & 1) ? q0 : q1;
    a += __shfl_xor_sync(FULL, b, 1);
    float c = (le & 1) ? q3 : q2;
    float d = (le & 1) ? q2 : q3;
    c += __shfl_xor_sync(FULL, d, 1);
    float e = (le & 2) ? c : a;
    float f = (le & 2) ? a : c;
    e += __shfl_xor_sync(FULL, f, 2);
    return e;
}

// ---------------------------------------------------------------------------
// Kernel 0: phi vector. 8 blocks x 1024 threads.
// Stage 1: h1 redundant per block, split-K x8, 4 chains.
// Stage 2: only outputs [S, 3S) are ever used; 32 outputs/block, 32 k-chunks.
// Also zeros the graph accumulator.
// ---------------------------------------------------------------------------
__global__ void __launch_bounds__(1024) k_phi(
        const float* __restrict__ emb0,
        const float* __restrict__ w1, const float* __restrict__ b1,
        const float* __restrict__ w2, const float* __restrict__ b2) {
    __shared__ float se[S];
    __shared__ float part1[8][S];
    __shared__ float h1[S];
    __shared__ float part2[32][32];
    int t = threadIdx.x;
    int b = blockIdx.x;

    for (int i = b * 1024 + t; i < GMAX * S; i += PHI_BLOCKS * 1024)
        g_graph[i] = 0.0f;

    if (t < S) se[t] = 128.0f * emb0[t];
    __syncthreads();

    // stage 1: f = t&127, q = t>>7 (0..7), chunk of 16 k, 4 chains
    {
        int f = t & 127;
        int q = t >> 7;
        int k0 = q * 16;
        float a0 = 0.0f, a1 = 0.0f, a2 = 0.0f, a3 = 0.0f;
        #pragma unroll
        for (int i = 0; i < 16; i += 4) {
            a0 += se[k0 + i + 0] * w1[(k0 + i + 0) * S + f];
            a1 += se[k0 + i + 1] * w1[(k0 + i + 1) * S + f];
            a2 += se[k0 + i + 2] * w1[(k0 + i + 2) * S + f];
            a3 += se[k0 + i + 3] * w1[(k0 + i + 3) * S + f];
        }
        part1[q][f] = (a0 + a1) + (a2 + a3);
    }
    __syncthreads();
    if (t < S) {
        float s = b1[t];
        #pragma unroll
        for (int j = 0; j < 8; j++) s += part1[j][t];
        h1[t] = siluf(s);
    }
    __syncthreads();

    // stage 2: block b owns outputs [S + b*32, S + b*32 + 32); 32 k-chunks of 4
    {
        int ol = t & 31;
        int q = t >> 5;          // 0..31
        int o = S + b * 32 + ol;
        int k0 = q * 4;
        float a0 = h1[k0 + 0] * w2[(k0 + 0) * 3 * S + o]
                 + h1[k0 + 2] * w2[(k0 + 2) * 3 * S + o];
        float a1 = h1[k0 + 1] * w2[(k0 + 1) * 3 * S + o]
                 + h1[k0 + 3] * w2[(k0 + 3) * 3 * S + o];
        part2[q][ol] = a0 + a1;
    }
    __syncthreads();
    if (t < 32) {
        int o = S + b * 32 + t;
        float s = b2[o];
        #pragma unroll
        for (int j = 0; j < 32; j++) s += part2[j][t];
        g_phi[o] = s;
    }
}

// ---------------------------------------------------------------------------
// Fused kernel: edge stats + filter dots -> tiles -> per-node MLP -> atomics.
// ---------------------------------------------------------------------------
__global__ void __launch_bounds__(256, 2) k_main(
        const float* __restrict__ diffs, const float* __restrict__ lens,
        const float* __restrict__ filt_w, const float* __restrict__ filt_b,
        const float* __restrict__ u_w, const float* __restrict__ v_w,
        const float* __restrict__ w1, const float* __restrict__ b1,
        const float* __restrict__ w2, const float* __restrict__ b2,
        const int* __restrict__ gidx, int N) {
    extern __shared__ __align__(16) float sm[];
    float* bufA = sm + OFF_BUFA;
    float* bufB = sm + OFF_BUFB;
    float* sA   = sm + OFF_SA;
    float* sB   = sm + OFF_SB;
    float* sAb  = sm + OFF_SAB;
    float* sBb  = sm + OFF_SBB;
    float* sInv = sm + OFF_SINV;
    float* scp  = sm + OFF_SCP;
    float* sc   = sm + OFF_SC;
    int* sgidx  = (int*)(sm + OFF_GIDX);

    const unsigned FULL = 0xffffffffu;
    int t = threadIdx.x;
    int f = t & 127;
    int h = t >> 7;
    int colbase = NCOL * h;
    int n0 = blockIdx.x * BN;

    if (t < BN) sgidx[t] = gidx[min(n0 + t, N - 1)];

    // ---- Edge stage: 4 lanes/node, 4 edges/lane ----
    {
        int gi = t >> 2;
        int le = t & 3;
        bool valid = gi < BN;
        int nc = min(n0 + min(gi, BN - 1), N - 1);
        int e0 = nc * DEG + le * 4;
        const float4* dp = (const float4*)(diffs + 3 * e0);
        float4 d0 = dp[0], d1 = dp[1], d2 = dp[2];
        float4 lv = *(const float4*)(lens + e0);
        float dx[4] = {d0.x, d0.w, d1.z, d2.y};
        float dy[4] = {d0.y, d1.x, d1.w, d2.z};
        float dz[4] = {d0.z, d1.y, d2.x, d2.w};
        float ln[4] = {lv.x, lv.y, lv.z, lv.w};
        float pir[4], pre[4], sk[4], skm[4], cc[4];
        float fr = 0.0f;
        #pragma unroll
        for (int j = 0; j < 4; j++) {
            float r2 = dx[j] * dx[j] + dy[j] * dy[j] + dz[j] * dz[j];
            float r = sqrtf(r2);
            float m = (fabsf(ln[j]) <= 10.0f) ? 1.0f : 0.0f;
            float rs = fmaxf(r, 1e-12f);
            float bq = rs * 0.1f;
            float c = cospif(bq);
            float s = sinpif(bq);
            float cut = (r < 10.0f) ? 0.5f * (c + 1.0f) : 0.0f;
            pre[j] = m * cut;
            pir[j] = m * cut / rs;
            sk[j] = s; skm[j] = 0.0f; cc[j] = 2.0f * c;
            fr += m * r2;
        }
        fr += __shfl_xor_sync(FULL, fr, 1);
        fr += __shfl_xor_sync(FULL, fr, 2);
        if (valid && le == 0) {
            float frob = sqrtf(fr);
            sInv[gi] = 1.0f / ((frob > 0.0f) ? frob : 1.0f);
        }
        {
            float q0 = pre[0] + pre[1] + pre[2] + pre[3];
            float q1 = pre[0] * dx[0] + pre[1] * dx[1] + pre[2] * dx[2] + pre[3] * dx[3];
            float q2 = pre[0] * dy[0] + pre[1] * dy[1] + pre[2] * dy[2] + pre[3] * dy[3];
            float q3 = pre[0] * dz[0] + pre[1] * dz[1] + pre[2] * dz[2] + pre[3] * dz[3];
            float v = bf4x4(q0, q1, q2, q3, le);
            if (valid) {
                if (le == 0) sAb[gi] = v;
                else sBb[gi * 3 + le - 1] = v;
            }
        }
        #pragma unroll
        for (int k = 0; k < NRBF; k++) {
            float a0 = pir[0] * sk[0];
            float a1 = pir[1] * sk[1];
            float a2 = pir[2] * sk[2];
            float a3 = pir[3] * sk[3];
            float q0 = (a0 + a1) + (a2 + a3);
            float q1 = a0 * dx[0] + a1 * dx[1] + a2 * dx[2] + a3 * dx[3];
            float q2 = a0 * dy[0] + a1 * dy[1] + a2 * dy[2] + a3 * dy[3];
            float q3 = a0 * dz[0] + a1 * dz[1] + a2 * dz[2] + a3 * dz[3];
            float v = bf4x4(q0, q1, q2, q3, le);
            if (valid) {
                if (le == 0) sA[gi * NRBF + k] = v;
                else sB[(gi * 3 + le - 1) * NRBF + k] = v;
            }
            #pragma unroll
            for (int j = 0; j < 4; j++) {
                float sn = cc[j] * sk[j] - skm[j];
                skm[j] = sk[j];
                sk[j] = sn;
            }
        }
    }
    __syncthreads();

    // ---- Filter dots -> tiles ----
    {
        int c = f % 3;
        float phi2 = g_phi[S + f];
        float phi3 = g_phi[2 * S + f];
        float fb2 = filt_b[S + f];
        float fb3 = filt_b[2 * S + f];

        ull w2p[NRBF / 2], w3p[NRBF / 2];
        #pragma unroll
        for (int kk = 0; kk < NRBF / 2; kk++) {
            w2p[kk] = pack2(filt_w[(2 * kk) * 3 * S + S + f],
                            filt_w[(2 * kk + 1) * 3 * S + S + f]);
            w3p[kk] = pack2(filt_w[(2 * kk) * 3 * S + 2 * S + f],
                            filt_w[(2 * kk + 1) * 3 * S + 2 * S + f]);
        }
        #pragma unroll
        for (int ni = 0; ni < NCOL; ni++) {
            int col = colbase + ni;
            ull acc2 = 0ull, acc3 = 0ull;
            const ull* pa = (const ull*)&sA[col * NRBF];
            const ull* pb = (const ull*)&sB[(col * 3 + c) * NRBF];
            #pragma unroll
            for (int kk = 0; kk < NRBF / 2; kk++) {
                acc2 = ffma2(pa[kk], w2p[kk], acc2);
                acc3 = ffma2(pb[kk], w3p[kk], acc3);
            }
            float a2l, a2h, a3l, a3h;
            unpack2(acc2, a2l, a2h);
            unpack2(acc3, a3l, a3h);
            bufB[f * BW + col] = phi2 * (a2l + a2h + sAb[col] * fb2);
            bufA[f * BW + col] = phi3 * (a3l + a3h + sBb[col * 3 + c] * fb3) * sInv[col];
        }
    }
    __syncthreads();

    // ---- U, V matmuls ----
    ull aU[NACC], aV[NACC];
    #pragma unroll
    for (int j = 0; j < NACC; j++) { aU[j] = 0ull; aV[j] = 0ull; }
    #pragma unroll 2
    for (int s = 0; s < S; s++) {
        float wu = u_w[s * S + f];
        float wv = v_w[s * S + f];
        ull wuu = pack2(wu, wu), wvv = pack2(wv, wv);
        const ull* row = (const ull*)&bufA[s * BW + colbase];
        #pragma unroll
        for (int j = 0; j < NACC; j++) {
            ull x = row[j];
            aU[j] = ffma2(x, wuu, aU[j]);
            aV[j] = ffma2(x, wvv, aV[j]);
        }
    }
    __syncthreads();

    const float SQ3 = 1.7320508075688772f;
    float prod[NCOL];
    #pragma unroll
    for (int j = 0; j < NACC; j++) {
        float u0, u1, v0, v1;
        unpack2(aU[j], u0, u1);
        unpack2(aV[j], v0, v1);
        prod[2 * j] = u0 * v0;
        prod[2 * j + 1] = u1 * v1;
        bufA[f * BW + colbase + 2 * j] = SQ3 * fabsf(v0);
        bufA[f * BW + colbase + 2 * j + 1] = SQ3 * fabsf(v1);
    }
    int w = t >> 5, lane = t & 31;
    #pragma unroll
    for (int ni = 0; ni < NCOL; ni++) {
        float v = prod[ni];
        #pragma unroll
        for (int m = 16; m; m >>= 1) v += __shfl_xor_sync(FULL, v, m);
        if (lane == 0) scp[w * NCOL + ni] = v;
    }
    __syncthreads();
    if (t < BN) {
        int hh = t / NCOL, ni = t % NCOL;
        int wb = hh * 4;
        sc[t] = scp[wb * NCOL + ni] + scp[(wb + 1) * NCOL + ni] +
                scp[(wb + 2) * NCOL + ni] + scp[(wb + 3) * NCOL + ni];
    }
    __syncthreads();

    // ---- h = silu([Vnorm, state1] @ upd_w1 + b1) ----
    ull aH[NACC];
    #pragma unroll
    for (int j = 0; j < NACC; j++) aH[j] = 0ull;
    #pragma unroll 2
    for (int s = 0; s < S; s++) {
        float wA = w1[s * S + f];
        float wB = w1[(S + s) * S + f];
        ull wAA = pack2(wA, wA), wBB = pack2(wB, wB);
        const ull* rowA = (const ull*)&bufA[s * BW + colbase];
        const ull* rowB = (const ull*)&bufB[s * BW + colbase];
        #pragma unroll
        for (int j = 0; j < NACC; j++) {
            aH[j] = ffma2(rowA[j], wAA, aH[j]);
            aH[j] = ffma2(rowB[j], wBB, aH[j]);
        }
    }
    __syncthreads();
    {
        float bb = b1[f];
        #pragma unroll
        for (int j = 0; j < NACC; j++) {
            float h0, h1v;
            unpack2(aH[j], h0, h1v);
            bufA[f * BW + colbase + 2 * j] = siluf(h0 + bb);
            bufA[f * BW + colbase + 2 * j + 1] = siluf(h1v + bb);
        }
    }
    __syncthreads();

    // ---- a_sv, a_ss; final state -> REDG into graph accumulator ----
    ull aSV[NACC], aSS[NACC];
    #pragma unroll
    for (int j = 0; j < NACC; j++) { aSV[j] = 0ull; aSS[j] = 0ull; }
    #pragma unroll 2
    for (int s = 0; s < S; s++) {
        float wsv = w2[s * 3 * S + S + f];
        float wss = w2[s * 3 * S + 2 * S + f];
        ull wv2 = pack2(wsv, wsv), ws2 = pack2(wss, wss);
        const ull* row = (const ull*)&bufA[s * BW + colbase];
        #pragma unroll
        for (int j = 0; j < NACC; j++) {
            ull x = row[j];
            aSV[j] = ffma2(x, wv2, aSV[j]);
            aSS[j] = ffma2(x, ws2, aSS[j]);
        }
    }
    {
        float bsv = b2[S + f];
        float bss = b2[2 * S + f];
        #pragma unroll
        for (int j = 0; j < NACC; j++) {
            float sv0, sv1, ss0, ss1;
            unpack2(aSV[j], sv0, sv1);
            unpack2(aSS[j], ss0, ss1);
            int col = colbase + 2 * j;
            int nn0 = n0 + col;
            if (nn0 < N) {
                float v = (ss0 + bss) + 3.0f * sc[col] * (sv0 + bsv);
                atomicAdd(&g_graph[sgidx[col] * S + f], v);
            }
            if (nn0 + 1 < N) {
                float v = (ss1 + bss) + 3.0f * sc[col + 1] * (sv1 + bsv);
                atomicAdd(&g_graph[sgidx[col + 1] * S + f], v);
            }
        }
    }
}

// ---------------------------------------------------------------------------
// Output MLP per graph: 512 threads, split-K x4, 4 chains
// ---------------------------------------------------------------------------
__global__ void __launch_bounds__(512) k_out(
        const float* __restrict__ w1, const float* __restrict__ b1,
        const float* __restrict__ w2, const float* __restrict__ b2,
        float* __restrict__ out) {
    __shared__ float gs[S];
    __shared__ float part[4][S];
    __shared__ float red[4];
    int g = blockIdx.x, t = threadIdx.x;
    int f = t & 127;
    int q = t >> 7;
    if (t < S) gs[t] = g_graph[g * S + t];
    __syncthreads();
    int sbase = q * 32;
    float a0 = 0.0f, a1 = 0.0f, a2 = 0.0f, a3 = 0.0f;
    #pragma unroll
    for (int i = 0; i < 32; i += 4) {
        a0 += gs[sbase + i + 0] * w1[(sbase + i + 0) * S + f];
        a1 += gs[sbase + i + 1] * w1[(sbase + i + 1) * S + f];
        a2 += gs[sbase + i + 2] * w1[(sbase + i + 2) * S + f];
        a3 += gs[sbase + i + 3] * w1[(sbase + i + 3) * S + f];
    }
    part[q][f] = (a0 + a1) + (a2 + a3);
    __syncthreads();
    if (t < S) {
        float hacc = b1[t] + (part[0][t] + part[1][t]) + (part[2][t] + part[3][t]);
        float h = hacc / (1.0f + expf(-hacc));
        float p = h * w2[t];
        #pragma unroll
        for (int m = 16; m; m >>= 1) p += __shfl_xor_sync(0xffffffffu, p, m);
        int w = t >> 5, lane = t & 31;
        if (lane == 0) red[w] = p;
    }
    __syncthreads();
    if (t == 0) out[g] = red[0] + red[1] + red[2] + red[3] + b2[0];
}

// ---------------------------------------------------------------------------
extern "C" void kernel_launch(void* const* d_in, const int* in_sizes, int n_in,
                              void* d_out, int out_size) {
    int N = in_sizes[3];
    int off = (n_in >= 22) ? 1 : 0;

    const float* diffs   = (const float*)d_in[0];
    const float* lens    = (const float*)d_in[1];
    const int*   gidx    = (const int*)d_in[3];
    const float* emb0    = (const float*)d_in[4 + off];
    const float* phi_w1  = (const float*)d_in[5 + off];
    const float* phi_b1  = (const float*)d_in[6 + off];
    const float* phi_w2  = (const float*)d_in[7 + off];
    const float* phi_b2  = (const float*)d_in[8 + off];
    const float* filt_w  = (const float*)d_in[9 + off];
    const float* filt_b  = (const float*)d_in[10 + off];
    const float* u_w     = (const float*)d_in[11 + off];
    const float* v_w     = (const float*)d_in[12 + off];
    const float* upd_w1  = (const float*)d_in[13 + off];
    const float* upd_b1  = (const float*)d_in[14 + off];
    const float* upd_w2  = (const float*)d_in[15 + off];
    const float* upd_b2  = (const float*)d_in[16 + off];
    const float* out_w1  = (const float*)d_in[17 + off];
    const float* out_b1  = (const float*)d_in[18 + off];
    const float* out_w2  = (const float*)d_in[19 + off];
    const float* out_b2  = (const float*)d_in[20 + off];
    float* out = (float*)d_out;
    int G = out_size;

    cudaFuncSetAttribute(k_main, cudaFuncAttributeMaxDynamicSharedMemorySize,
                         SMEM_BYTES);

    k_phi<<<PHI_BLOCKS, 1024>>>(emb0, phi_w1, phi_b1, phi_w2, phi_b2);

    int nblk = (N + BN - 1) / BN;
    k_main<<<nblk, 256, SMEM_BYTES>>>(diffs, lens, filt_w, filt_b,
                                      u_w, v_w, upd_w1, upd_b1, upd_w2, upd_b2,
                                      gidx, N);

    k_out<<<G, 512>>>(out_w1, out_b1, out_w2, out_b2, out);
}

// round 11
// speedup vs baseline: 1.8739x; 1.0518x over previous
#include <cuda_runtime.h>
#include <math.h>

#define S 128
#define NRBF 20
#define DEG 16
#define BN 36         // nodes per block (278 blocks = 1 wave @ 2/SM)
#define NCOL 18       // columns per 128-thread half
#define NACC 9        // f32x2 accumulators per half
#define SLICE 24      // floats per half-row slice (96B, 16B-aligned)
#define BWF 48        // floats per row (2 slices)
#define GMAX 64
#define PHI_BLOCKS 8

__device__ float g_phi[3 * S];
__device__ float g_graph[GMAX * S];

typedef unsigned long long ull;

// dynamic smem layout (floats)
#define OFF_BUFA 0
#define OFF_BUFB (S * BWF)
#define OFF_SA   (2 * S * BWF)
#define OFF_SB   (OFF_SA + BN * NRBF)
#define OFF_SAB  (OFF_SB + BN * 3 * NRBF)
#define OFF_SBB  (OFF_SAB + BN)
#define OFF_SINV (OFF_SBB + 3 * BN)
#define OFF_SCP  (OFF_SINV + BN)
#define OFF_SC   (OFF_SCP + 8 * NCOL)
#define OFF_GIDX (OFF_SC + BN)
#define SMEM_FLOATS (OFF_GIDX + BN)
#define SMEM_BYTES (SMEM_FLOATS * 4)

__device__ __forceinline__ float siluf(float x) {
    return x / (1.0f + __expf(-x));
}
__device__ __forceinline__ ull pack2(float a, float b) {
    ull r;
    asm("mov.b64 %0, {%1,%2};" : "=l"(r) : "f"(a), "f"(b));
    return r;
}
__device__ __forceinline__ ull ffma2(ull a, ull b, ull c) {
    ull d;
    asm("fma.rn.f32x2 %0, %1, %2, %3;" : "=l"(d) : "l"(a), "l"(b), "l"(c));
    return d;
}
__device__ __forceinline__ void unpack2(ull p, float& lo, float& hi) {
    asm("mov.b64 {%0,%1}, %2;" : "=f"(lo), "=f"(hi) : "l"(p));
}

// load 18 floats (9 ulls) from a 16B-aligned slice: 4x LDS.128 + 1x LDS.64
__device__ __forceinline__ void load_row9(const float* base, ull* x) {
    const ulonglong2* p2 = (const ulonglong2*)base;
    ulonglong2 a = p2[0], b = p2[1], c = p2[2], d = p2[3];
    x[0] = a.x; x[1] = a.y; x[2] = b.x; x[3] = b.y;
    x[4] = c.x; x[5] = c.y; x[6] = d.x; x[7] = d.y;
    x[8] = ((const ull*)base)[8];
}

// 4-lane 4-channel butterfly
__device__ __forceinline__ float bf4x4(float q0, float q1, float q2, float q3, int le) {
    const unsigned FULL = 0xffffffffu;
    float a = (le & 1) ? q1 : q0;
    float b = (le & 1) ? q0 : q1;
    a += __shfl_xor_sync(FULL, b, 1);
    float c = (le & 1) ? q3 : q2;
    float d = (le & 1) ? q2 : q3;
    c += __shfl_xor_sync(FULL, d, 1);
    float e = (le & 2) ? c : a;
    float f = (le & 2) ? a : c;
    e += __shfl_xor_sync(FULL, f, 2);
    return e;
}

// ---------------------------------------------------------------------------
// Kernel 0: phi vector. 8 blocks x 1024 threads. (frozen from R10)
// ---------------------------------------------------------------------------
__global__ void __launch_bounds__(1024) k_phi(
        const float* __restrict__ emb0,
        const float* __restrict__ w1, const float* __restrict__ b1,
        const float* __restrict__ w2, const float* __restrict__ b2) {
    __shared__ float se[S];
    __shared__ float part1[8][S];
    __shared__ float h1[S];
    __shared__ float part2[32][32];
    int t = threadIdx.x;
    int b = blockIdx.x;

    for (int i = b * 1024 + t; i < GMAX * S; i += PHI_BLOCKS * 1024)
        g_graph[i] = 0.0f;

    if (t < S) se[t] = 128.0f * emb0[t];
    __syncthreads();

    {
        int f = t & 127;
        int q = t >> 7;
        int k0 = q * 16;
        float a0 = 0.0f, a1 = 0.0f, a2 = 0.0f, a3 = 0.0f;
        #pragma unroll
        for (int i = 0; i < 16; i += 4) {
            a0 += se[k0 + i + 0] * w1[(k0 + i + 0) * S + f];
            a1 += se[k0 + i + 1] * w1[(k0 + i + 1) * S + f];
            a2 += se[k0 + i + 2] * w1[(k0 + i + 2) * S + f];
            a3 += se[k0 + i + 3] * w1[(k0 + i + 3) * S + f];
        }
        part1[q][f] = (a0 + a1) + (a2 + a3);
    }
    __syncthreads();
    if (t < S) {
        float s = b1[t];
        #pragma unroll
        for (int j = 0; j < 8; j++) s += part1[j][t];
        h1[t] = t < S ? (s / (1.0f + expf(-s))) : 0.0f;
    }
    __syncthreads();

    {
        int ol = t & 31;
        int q = t >> 5;
        int o = S + b * 32 + ol;
        int k0 = q * 4;
        float a0 = h1[k0 + 0] * w2[(k0 + 0) * 3 * S + o]
                 + h1[k0 + 2] * w2[(k0 + 2) * 3 * S + o];
        float a1 = h1[k0 + 1] * w2[(k0 + 1) * 3 * S + o]
                 + h1[k0 + 3] * w2[(k0 + 3) * 3 * S + o];
        part2[q][ol] = a0 + a1;
    }
    __syncthreads();
    if (t < 32) {
        int o = S + b * 32 + t;
        float s = b2[o];
        #pragma unroll
        for (int j = 0; j < 32; j++) s += part2[j][t];
        g_phi[o] = s;
    }
}

// ---------------------------------------------------------------------------
// Fused kernel: edge stats + filter dots -> aligned tiles -> MLP -> atomics.
// ---------------------------------------------------------------------------
__global__ void __launch_bounds__(256, 2) k_main(
        const float* __restrict__ diffs, const float* __restrict__ lens,
        const float* __restrict__ filt_w, const float* __restrict__ filt_b,
        const float* __restrict__ u_w, const float* __restrict__ v_w,
        const float* __restrict__ w1, const float* __restrict__ b1,
        const float* __restrict__ w2, const float* __restrict__ b2,
        const int* __restrict__ gidx, int N) {
    extern __shared__ __align__(16) float sm[];
    float* bufA = sm + OFF_BUFA;
    float* bufB = sm + OFF_BUFB;
    float* sA   = sm + OFF_SA;
    float* sB   = sm + OFF_SB;
    float* sAb  = sm + OFF_SAB;
    float* sBb  = sm + OFF_SBB;
    float* sInv = sm + OFF_SINV;
    float* scp  = sm + OFF_SCP;
    float* sc   = sm + OFF_SC;
    int* sgidx  = (int*)(sm + OFF_GIDX);

    const unsigned FULL = 0xffffffffu;
    int t = threadIdx.x;
    int f = t & 127;
    int h = t >> 7;
    int colbase = NCOL * h;
    int n0 = blockIdx.x * BN;

    if (t < BN) sgidx[t] = gidx[min(n0 + t, N - 1)];

    // ---- Edge stage: 4 lanes/node, 4 edges/lane ----
    {
        int gi = t >> 2;
        int le = t & 3;
        bool valid = gi < BN;
        int nc = min(n0 + min(gi, BN - 1), N - 1);
        int e0 = nc * DEG + le * 4;
        const float4* dp = (const float4*)(diffs + 3 * e0);
        float4 d0 = dp[0], d1 = dp[1], d2 = dp[2];
        float4 lv = *(const float4*)(lens + e0);
        float dx[4] = {d0.x, d0.w, d1.z, d2.y};
        float dy[4] = {d0.y, d1.x, d1.w, d2.z};
        float dz[4] = {d0.z, d1.y, d2.x, d2.w};
        float ln[4] = {lv.x, lv.y, lv.z, lv.w};
        float pir[4], pre[4], sk[4], skm[4], cc[4];
        float fr = 0.0f;
        #pragma unroll
        for (int j = 0; j < 4; j++) {
            float r2 = dx[j] * dx[j] + dy[j] * dy[j] + dz[j] * dz[j];
            float r = sqrtf(r2);
            float m = (fabsf(ln[j]) <= 10.0f) ? 1.0f : 0.0f;
            float rs = fmaxf(r, 1e-12f);
            float bq = rs * 0.1f;
            float c = cospif(bq);
            float s = sinpif(bq);
            float cut = (r < 10.0f) ? 0.5f * (c + 1.0f) : 0.0f;
            pre[j] = m * cut;
            pir[j] = m * cut / rs;
            sk[j] = s; skm[j] = 0.0f; cc[j] = 2.0f * c;
            fr += m * r2;
        }
        fr += __shfl_xor_sync(FULL, fr, 1);
        fr += __shfl_xor_sync(FULL, fr, 2);
        if (valid && le == 0) {
            float frob = sqrtf(fr);
            sInv[gi] = 1.0f / ((frob > 0.0f) ? frob : 1.0f);
        }
        {
            float q0 = pre[0] + pre[1] + pre[2] + pre[3];
            float q1 = pre[0] * dx[0] + pre[1] * dx[1] + pre[2] * dx[2] + pre[3] * dx[3];
            float q2 = pre[0] * dy[0] + pre[1] * dy[1] + pre[2] * dy[2] + pre[3] * dy[3];
            float q3 = pre[0] * dz[0] + pre[1] * dz[1] + pre[2] * dz[2] + pre[3] * dz[3];
            float v = bf4x4(q0, q1, q2, q3, le);
            if (valid) {
                if (le == 0) sAb[gi] = v;
                else sBb[gi * 3 + le - 1] = v;
            }
        }
        #pragma unroll
        for (int k = 0; k < NRBF; k++) {
            float a0 = pir[0] * sk[0];
            float a1 = pir[1] * sk[1];
            float a2 = pir[2] * sk[2];
            float a3 = pir[3] * sk[3];
            float q0 = (a0 + a1) + (a2 + a3);
            float q1 = a0 * dx[0] + a1 * dx[1] + a2 * dx[2] + a3 * dx[3];
            float q2 = a0 * dy[0] + a1 * dy[1] + a2 * dy[2] + a3 * dy[3];
            float q3 = a0 * dz[0] + a1 * dz[1] + a2 * dz[2] + a3 * dz[3];
            float v = bf4x4(q0, q1, q2, q3, le);
            if (valid) {
                if (le == 0) sA[gi * NRBF + k] = v;
                else sB[(gi * 3 + le - 1) * NRBF + k] = v;
            }
            #pragma unroll
            for (int j = 0; j < 4; j++) {
                float sn = cc[j] * sk[j] - skm[j];
                skm[j] = sk[j];
                sk[j] = sn;
            }
        }
    }
    __syncthreads();

    // ---- Filter dots -> tiles (pairs, packed STS.64) ----
    {
        int c = f % 3;
        float phi2 = g_phi[S + f];
        float phi3 = g_phi[2 * S + f];
        float fb2 = filt_b[S + f];
        float fb3 = filt_b[2 * S + f];
        float* rowA = bufA + (f * 2 + h) * SLICE;
        float* rowB = bufB + (f * 2 + h) * SLICE;

        ull w2p[NRBF / 2], w3p[NRBF / 2];
        #pragma unroll
        for (int kk = 0; kk < NRBF / 2; kk++) {
            w2p[kk] = pack2(filt_w[(2 * kk) * 3 * S + S + f],
                            filt_w[(2 * kk + 1) * 3 * S + S + f]);
            w3p[kk] = pack2(filt_w[(2 * kk) * 3 * S + 2 * S + f],
                            filt_w[(2 * kk + 1) * 3 * S + 2 * S + f]);
        }
        #pragma unroll
        for (int ni = 0; ni < NCOL; ni += 2) {
            int col0 = colbase + ni;
            int col1 = col0 + 1;
            ull a2x = 0ull, a2y = 0ull, a3x = 0ull, a3y = 0ull;
            const ull* pa0 = (const ull*)&sA[col0 * NRBF];
            const ull* pa1 = (const ull*)&sA[col1 * NRBF];
            const ull* pb0 = (const ull*)&sB[(col0 * 3 + c) * NRBF];
            const ull* pb1 = (const ull*)&sB[(col1 * 3 + c) * NRBF];
            #pragma unroll
            for (int kk = 0; kk < NRBF / 2; kk++) {
                a2x = ffma2(pa0[kk], w2p[kk], a2x);
                a2y = ffma2(pa1[kk], w2p[kk], a2y);
                a3x = ffma2(pb0[kk], w3p[kk], a3x);
                a3y = ffma2(pb1[kk], w3p[kk], a3y);
            }
            float xl, xh, yl, yh, ul, uh, vl, vh;
            unpack2(a2x, xl, xh);
            unpack2(a2y, yl, yh);
            unpack2(a3x, ul, uh);
            unpack2(a3y, vl, vh);
            float s0 = phi2 * (xl + xh + sAb[col0] * fb2);
            float s1 = phi2 * (yl + yh + sAb[col1] * fb2);
            float v0 = phi3 * (ul + uh + sBb[col0 * 3 + c] * fb3) * sInv[col0];
            float v1 = phi3 * (vl + vh + sBb[col1 * 3 + c] * fb3) * sInv[col1];
            *(ull*)(rowB + ni) = pack2(s0, s1);
            *(ull*)(rowA + ni) = pack2(v0, v1);
        }
    }
    __syncthreads();

    // ---- U, V matmuls ----
    ull aU[NACC], aV[NACC];
    #pragma unroll
    for (int j = 0; j < NACC; j++) { aU[j] = 0ull; aV[j] = 0ull; }
    #pragma unroll 2
    for (int s = 0; s < S; s++) {
        float wu = u_w[s * S + f];
        float wv = v_w[s * S + f];
        ull wuu = pack2(wu, wu), wvv = pack2(wv, wv);
        ull x[NACC];
        load_row9(bufA + (s * 2 + h) * SLICE, x);
        #pragma unroll
        for (int j = 0; j < NACC; j++) {
            aU[j] = ffma2(x[j], wuu, aU[j]);
            aV[j] = ffma2(x[j], wvv, aV[j]);
        }
    }
    __syncthreads();

    const float SQ3 = 1.7320508075688772f;
    float prod[NCOL];
    {
        float* rowA = bufA + (f * 2 + h) * SLICE;
        #pragma unroll
        for (int j = 0; j < NACC; j++) {
            float u0, u1, v0, v1;
            unpack2(aU[j], u0, u1);
            unpack2(aV[j], v0, v1);
            prod[2 * j] = u0 * v0;
            prod[2 * j + 1] = u1 * v1;
            *(ull*)(rowA + 2 * j) = pack2(SQ3 * fabsf(v0), SQ3 * fabsf(v1));
        }
    }
    int w = t >> 5, lane = t & 31;
    #pragma unroll
    for (int ni = 0; ni < NCOL; ni++) {
        float v = prod[ni];
        #pragma unroll
        for (int m = 16; m; m >>= 1) v += __shfl_xor_sync(FULL, v, m);
        if (lane == 0) scp[w * NCOL + ni] = v;
    }
    __syncthreads();
    if (t < BN) {
        int hh = t / NCOL, ni = t % NCOL;
        int wb = hh * 4;
        sc[t] = scp[wb * NCOL + ni] + scp[(wb + 1) * NCOL + ni] +
                scp[(wb + 2) * NCOL + ni] + scp[(wb + 3) * NCOL + ni];
    }
    __syncthreads();

    // ---- h = silu([Vnorm, state1] @ upd_w1 + b1) ----
    ull aH[NACC];
    #pragma unroll
    for (int j = 0; j < NACC; j++) aH[j] = 0ull;
    #pragma unroll 2
    for (int s = 0; s < S; s++) {
        float wA = w1[s * S + f];
        float wB = w1[(S + s) * S + f];
        ull wAA = pack2(wA, wA), wBB = pack2(wB, wB);
        ull xa[NACC], xb[NACC];
        load_row9(bufA + (s * 2 + h) * SLICE, xa);
        load_row9(bufB + (s * 2 + h) * SLICE, xb);
        #pragma unroll
        for (int j = 0; j < NACC; j++) {
            aH[j] = ffma2(xa[j], wAA, aH[j]);
            aH[j] = ffma2(xb[j], wBB, aH[j]);
        }
    }
    __syncthreads();
    {
        float bb = b1[f];
        float* rowA = bufA + (f * 2 + h) * SLICE;
        #pragma unroll
        for (int j = 0; j < NACC; j++) {
            float h0, h1v;
            unpack2(aH[j], h0, h1v);
            *(ull*)(rowA + 2 * j) = pack2(siluf(h0 + bb), siluf(h1v + bb));
        }
    }
    __syncthreads();

    // ---- a_sv, a_ss; final state -> REDG into graph accumulator ----
    ull aSV[NACC], aSS[NACC];
    #pragma unroll
    for (int j = 0; j < NACC; j++) { aSV[j] = 0ull; aSS[j] = 0ull; }
    #pragma unroll 2
    for (int s = 0; s < S; s++) {
        float wsv = w2[s * 3 * S + S + f];
        float wss = w2[s * 3 * S + 2 * S + f];
        ull wv2 = pack2(wsv, wsv), ws2 = pack2(wss, wss);
        ull x[NACC];
        load_row9(bufA + (s * 2 + h) * SLICE, x);
        #pragma unroll
        for (int j = 0; j < NACC; j++) {
            aSV[j] = ffma2(x[j], wv2, aSV[j]);
            aSS[j] = ffma2(x[j], ws2, aSS[j]);
        }
    }
    {
        float bsv = b2[S + f];
        float bss = b2[2 * S + f];
        #pragma unroll
        for (int j = 0; j < NACC; j++) {
            float sv0, sv1, ss0, ss1;
            unpack2(aSV[j], sv0, sv1);
            unpack2(aSS[j], ss0, ss1);
            int col = colbase + 2 * j;
            int nn0 = n0 + col;
            if (nn0 < N) {
                float v = (ss0 + bss) + 3.0f * sc[col] * (sv0 + bsv);
                atomicAdd(&g_graph[sgidx[col] * S + f], v);
            }
            if (nn0 + 1 < N) {
                float v = (ss1 + bss) + 3.0f * sc[col + 1] * (sv1 + bsv);
                atomicAdd(&g_graph[sgidx[col + 1] * S + f], v);
            }
        }
    }
}

// ---------------------------------------------------------------------------
// Output MLP per graph: 512 threads, split-K x4, 4 chains (frozen from R10)
// ---------------------------------------------------------------------------
__global__ void __launch_bounds__(512) k_out(
        const float* __restrict__ w1, const float* __restrict__ b1,
        const float* __restrict__ w2, const float* __restrict__ b2,
        float* __restrict__ out) {
    __shared__ float gs[S];
    __shared__ float part[4][S];
    __shared__ float red[4];
    int g = blockIdx.x, t = threadIdx.x;
    int f = t & 127;
    int q = t >> 7;
    if (t < S) gs[t] = g_graph[g * S + t];
    __syncthreads();
    int sbase = q * 32;
    float a0 = 0.0f, a1 = 0.0f, a2 = 0.0f, a3 = 0.0f;
    #pragma unroll
    for (int i = 0; i < 32; i += 4) {
        a0 += gs[sbase + i + 0] * w1[(sbase + i + 0) * S + f];
        a1 += gs[sbase + i + 1] * w1[(sbase + i + 1) * S + f];
        a2 += gs[sbase + i + 2] * w1[(sbase + i + 2) * S + f];
        a3 += gs[sbase + i + 3] * w1[(sbase + i + 3) * S + f];
    }
    part[q][f] = (a0 + a1) + (a2 + a3);
    __syncthreads();
    if (t < S) {
        float hacc = b1[t] + (part[0][t] + part[1][t]) + (part[2][t] + part[3][t]);
        float h = hacc / (1.0f + expf(-hacc));
        float p = h * w2[t];
        #pragma unroll
        for (int m = 16; m; m >>= 1) p += __shfl_xor_sync(0xffffffffu, p, m);
        int w = t >> 5, lane = t & 31;
        if (lane == 0) red[w] = p;
    }
    __syncthreads();
    if (t == 0) out[g] = red[0] + red[1] + red[2] + red[3] + b2[0];
}

// ---------------------------------------------------------------------------
extern "C" void kernel_launch(void* const* d_in, const int* in_sizes, int n_in,
                              void* d_out, int out_size) {
    int N = in_sizes[3];
    int off = (n_in >= 22) ? 1 : 0;

    const float* diffs   = (const float*)d_in[0];
    const float* lens    = (const float*)d_in[1];
    const int*   gidx    = (const int*)d_in[3];
    const float* emb0    = (const float*)d_in[4 + off];
    const float* phi_w1  = (const float*)d_in[5 + off];
    const float* phi_b1  = (const float*)d_in[6 + off];
    const float* phi_w2  = (const float*)d_in[7 + off];
    const float* phi_b2  = (const float*)d_in[8 + off];
    const float* filt_w  = (const float*)d_in[9 + off];
    const float* filt_b  = (const float*)d_in[10 + off];
    const float* u_w     = (const float*)d_in[11 + off];
    const float* v_w     = (const float*)d_in[12 + off];
    const float* upd_w1  = (const float*)d_in[13 + off];
    const float* upd_b1  = (const float*)d_in[14 + off];
    const float* upd_w2  = (const float*)d_in[15 + off];
    const float* upd_b2  = (const float*)d_in[16 + off];
    const float* out_w1  = (const float*)d_in[17 + off];
    const float* out_b1  = (const float*)d_in[18 + off];
    const float* out_w2  = (const float*)d_in[19 + off];
    const float* out_b2  = (const float*)d_in[20 + off];
    float* out = (float*)d_out;
    int G = out_size;

    cudaFuncSetAttribute(k_main, cudaFuncAttributeMaxDynamicSharedMemorySize,
                         SMEM_BYTES);

    k_phi<<<PHI_BLOCKS, 1024>>>(emb0, phi_w1, phi_b1, phi_w2, phi_b2);

    int nblk = (N + BN - 1) / BN;
    k_main<<<nblk, 256, SMEM_BYTES>>>(diffs, lens, filt_w, filt_b,
                                      u_w, v_w, upd_w1, upd_b1, upd_w2, upd_b2,
                                      gidx, N);

    k_out<<<G, 512>>>(out_w1, out_b1, out_w2, out_b2, out);
}